// round 13
// baseline (speedup 1.0000x reference)
#include <cuda_runtime.h>
#include <cuda_fp16.h>
#include <math.h>
#include <stdint.h>

// Problem constants
#define Bn 4
#define Tn 2048
#define Dn 1024
#define Hn 16
#define HDn 64
#define QKV_STRIDE (Bn * Hn * Tn * HDn)   // 8388608 elems per q/k/v

// ---------------------------------------------------------------------------
// Device scratch (no cudaMalloc allowed).  All u16 = fp16 bits.
// ---------------------------------------------------------------------------
__device__ unsigned short qkvh[3ull * QKV_STRIDE];      // [3][B][H][T][HD] fp16
__device__ unsigned short xa_h[(size_t)Bn * Tn * Dn];   // x fp16 [8192][1024]
__device__ unsigned short wq_h[(size_t)3 * Dn * Dn];    // Wqkv fp16 (native K-major)
__device__ unsigned short wo_h[(size_t)Dn * Dn];        // Wout fp16
__device__ unsigned short ga_h[(size_t)Bn * Tn * Dn];   // attention out fp16

// ---------------------------------------------------------------------------
// PTX helpers (non-arch-suffixed; valid on plain sm_103 target)
// ---------------------------------------------------------------------------
__device__ __forceinline__ uint32_t s2u(const void* p) {
    uint32_t a;
    asm("{ .reg .u64 t; cvta.to.shared.u64 t, %1; cvt.u32.u64 %0, t; }"
        : "=r"(a) : "l"(p));
    return a;
}
__device__ __forceinline__ void cpa16(uint32_t d, const void* s) {
    asm volatile("cp.async.cg.shared.global [%0], [%1], 16;"
                 :: "r"(d), "l"(s) : "memory");
}
__device__ __forceinline__ void cpa_commit() {
    asm volatile("cp.async.commit_group;" ::: "memory");
}
template<int N>
__device__ __forceinline__ void cpa_wait() {
    asm volatile("cp.async.wait_group %0;" :: "n"(N) : "memory");
}
__device__ __forceinline__ void ldsm4(uint32_t* r, uint32_t a) {
    asm volatile("ldmatrix.sync.aligned.m8n8.x4.shared.b16 {%0,%1,%2,%3}, [%4];"
        : "=r"(r[0]), "=r"(r[1]), "=r"(r[2]), "=r"(r[3]) : "r"(a));
}
__device__ __forceinline__ void ldsm4t(uint32_t* r, uint32_t a) {
    asm volatile("ldmatrix.sync.aligned.m8n8.x4.trans.shared.b16 {%0,%1,%2,%3}, [%4];"
        : "=r"(r[0]), "=r"(r[1]), "=r"(r[2]), "=r"(r[3]) : "r"(a));
}
__device__ __forceinline__ void mma16816(float* d, const uint32_t* a, const uint32_t* b) {
    asm volatile(
        "mma.sync.aligned.m16n8k16.row.col.f32.f16.f16.f32 "
        "{%0,%1,%2,%3}, {%4,%5,%6,%7}, {%8,%9}, {%0,%1,%2,%3};"
        : "+f"(d[0]), "+f"(d[1]), "+f"(d[2]), "+f"(d[3])
        : "r"(a[0]), "r"(a[1]), "r"(a[2]), "r"(a[3]), "r"(b[0]), "r"(b[1]));
}

// Swizzles
#define SWB(o) ((o) ^ ((((o) >> 8) & 7) << 4))   // 256B rows (GEMM B buf)
#define SW128(o) ((o) ^ ((((o) >> 7) & 7) << 4)) // 128B rows (GEMM A buf + attention)

// fp32 -> single fp16, fused over the three source arrays
__global__ __launch_bounds__(256)
void conv_fused_kernel(const float* __restrict__ x, unsigned short* __restrict__ xo,
                       const float* __restrict__ wq, unsigned short* __restrict__ wqo,
                       const float* __restrict__ wo, unsigned short* __restrict__ woo,
                       int nbx, int nbwq, int nbwo)
{
    const float* src;
    unsigned short* dst;
    int blk = blockIdx.x;
    if (blk < nbx) { src = x; dst = xo; }
    else if (blk < nbx + nbwq) { src = wq; dst = wqo; blk -= nbx; }
    else { src = wo; dst = woo; blk -= nbx + nbwq; }
    int i = blk * 256 + threadIdx.x;
    float4 v = ((const float4*)src)[i];
    __half a = __float2half_rn(v.x), b = __float2half_rn(v.y);
    __half c = __float2half_rn(v.z), d = __float2half_rn(v.w);
    ushort4 h;
    h.x = reinterpret_cast<unsigned short&>(a);
    h.y = reinterpret_cast<unsigned short&>(b);
    h.z = reinterpret_cast<unsigned short&>(c);
    h.w = reinterpret_cast<unsigned short&>(d);
    ((ushort4*)dst)[i] = h;
}

// ---------------------------------------------------------------------------
// Single-term fp16 GEMM via mma.sync: D[8192][NN] = Ah[8192][1024] @ Bh[1024][NN]
// 128x128 CTA tile, BK=64, 3-stage cp.async pipeline (32KB/stage), 8 warps
// (4m x 2n), warp tile 32x64, 64 MMAs per k-block, one sync per k-block.
// 2 CTAs/SM enforced.  MODE 0: fp16 scatter into qkvh.  MODE 1: fp32 write.
// ---------------------------------------------------------------------------
#define BK 64
#define NKB2 16                        // 1024 / 64
#define STAGES 3
#define ABUF 16384                     // 128 rows x 64 fp16 (128B rows)
#define BBUF 16384                     // 64 rows x 128 fp16 (256B rows)
#define STG_BYTES (ABUF + BBUF)        // 32768

template<int MODE, int NN>
__global__ __launch_bounds__(256, 2)
void tc_gemm(const unsigned short* __restrict__ Ah,
             const unsigned short* __restrict__ Bh, float* __restrict__ Cout)
{
    extern __shared__ __align__(1024) unsigned char gsm[];
    const uint32_t sbase = s2u(gsm);
    const int tid = threadIdx.x;
    const int lane = tid & 31, wid = tid >> 5;
    const int wm = wid & 3, wn = wid >> 2;
    const int bm = blockIdx.y * 128, bn = blockIdx.x * 128;

    const unsigned short* Abase = Ah + (size_t)bm * 1024;
    const unsigned short* Bbase = Bh + bn;

    auto load_stage = [&](int st, int kb) {
        uint32_t sb = sbase + st * STG_BYTES;
#pragma unroll
        for (int i = 0; i < 4; i++) {
            int id = i * 256 + tid;
            int r = id >> 3, c = id & 7;
            cpa16(sb + SW128(r * 128 + c * 16),
                  Abase + (size_t)r * 1024 + kb * BK + c * 8);
        }
#pragma unroll
        for (int i = 0; i < 4; i++) {
            int id = i * 256 + tid;
            int rk = id >> 4, cc = id & 15;
            cpa16(sb + ABUF + SWB(rk * 256 + cc * 16),
                  Bbase + (size_t)(kb * BK + rk) * NN + cc * 8);
        }
    };

    float acc[2][8][4];
#pragma unroll
    for (int mt = 0; mt < 2; mt++)
#pragma unroll
        for (int nt = 0; nt < 8; nt++)
#pragma unroll
            for (int q = 0; q < 4; q++) acc[mt][nt][q] = 0.f;

    load_stage(0, 0); cpa_commit();
    load_stage(1, 1); cpa_commit();

    const int a_lr = lane & 15;
    const int a_hk = (lane >> 4) << 4;

    for (int kb = 0; kb < NKB2; kb++) {
        const int cur = kb % STAGES;
        cpa_wait<1>();
        __syncthreads();
        if (kb + 2 < NKB2) load_stage((kb + 2) % STAGES, kb + 2);
        cpa_commit();

        uint32_t sb = sbase + cur * STG_BYTES;
#pragma unroll
        for (int ks = 0; ks < 4; ks++) {
            uint32_t afr[2][4];
#pragma unroll
            for (int mt = 0; mt < 2; mt++) {
                int r = wm * 32 + mt * 16 + a_lr;
                ldsm4(afr[mt], sb + SW128(r * 128 + ks * 32 + a_hk));
            }
            uint32_t bfr[8][2];
#pragma unroll
            for (int nt2 = 0; nt2 < 4; nt2++) {
                int kk = ks * 16 + a_lr;
                int nb = wn * 128 + nt2 * 32 + a_hk;
                uint32_t t[4];
                ldsm4t(t, sb + ABUF + SWB(kk * 256 + nb));
                bfr[nt2 * 2][0] = t[0]; bfr[nt2 * 2][1] = t[1];
                bfr[nt2 * 2 + 1][0] = t[2]; bfr[nt2 * 2 + 1][1] = t[3];
            }
#pragma unroll
            for (int mt = 0; mt < 2; mt++)
#pragma unroll
                for (int nt = 0; nt < 8; nt++)
                    mma16816(acc[mt][nt], afr[mt], bfr[nt]);
        }
    }

    const int gid = lane >> 2, tg = lane & 3;
#pragma unroll
    for (int mt = 0; mt < 2; mt++)
#pragma unroll
        for (int nt = 0; nt < 8; nt++) {
            int row0 = bm + wm * 32 + mt * 16 + gid;
            int col = bn + wn * 64 + nt * 8 + tg * 2;
#pragma unroll
            for (int half = 0; half < 2; half++) {
                int row = row0 + half * 8;
                float v0 = acc[mt][nt][half * 2], v1 = acc[mt][nt][half * 2 + 1];
                if (MODE == 0) {
                    int s = col >> 10, h = (col >> 6) & 15, d = col & 63;
                    int b = row >> 11, t = row & 2047;
                    size_t idx = (size_t)s * QKV_STRIDE +
                                 (((size_t)(b * Hn + h) * Tn + t) << 6) + d;
                    __half h0 = __float2half_rn(v0), h1 = __float2half_rn(v1);
                    *(uint32_t*)&qkvh[idx] =
                        (uint32_t)reinterpret_cast<unsigned short&>(h0) |
                        ((uint32_t)reinterpret_cast<unsigned short&>(h1) << 16);
                } else {
                    *(float2*)&Cout[(size_t)row * NN + col] = make_float2(v0, v1);
                }
            }
        }
}

// ---------------------------------------------------------------------------
// Tensor-core flash attention, single-term fp16 (fp32 accum).
// 256 threads = 8 warps; 128 q rows per block.  2 CTAs/SM.
// KV staged 128 tokens at a time (two 64-token sub-blocks per barrier),
// sorted-position sub-block skip, warp-uniform rescale skip, raw-logit
// softmax with scale folded into exp, descending tile order.
// ---------------------------------------------------------------------------
#define AQ_OFF 0                     // Q 16KB (128 rows x 128B)
#define AKV_OFF 16384                // 2 stages x (K 16KB + V 16KB)
#define APOS_OFF (16384 + 65536)     // 81920, 2 x 512B
#define ATTN_SMEM_SZ (16384 + 65536 + 1024)

__global__ __launch_bounds__(256, 2)
void attn_mma(const int* __restrict__ pos)
{
    extern __shared__ __align__(1024) unsigned char am[];
    const uint32_t sb = s2u(am);
    const int tid = threadIdx.x, lane = tid & 31, wm = tid >> 5;   // wm 0..7
    const int b = blockIdx.y >> 4, h = blockIdx.y & 15;
    const int i0 = (15 - blockIdx.x) * 128;    // heavy tiles scheduled first

    const size_t bh_off = ((size_t)(b * Hn + h) * Tn) << 6;
    const unsigned short* Qhg = qkvh + bh_off + ((size_t)i0 << 6);
    const unsigned short* Khg = qkvh + (size_t)QKV_STRIDE + bh_off;
    const unsigned short* Vhg = qkvh + 2ull * QKV_STRIDE + bh_off;
    const int* posb = pos + b * Tn;

    // Q tile (128 rows) -> smem: 1024 16B-chunks
#pragma unroll
    for (int i = 0; i < 4; i++) {
        int id = tid + i * 256;
        int r = id >> 3, c = id & 7;
        cpa16(sb + AQ_OFF + SW128(r * 128 + c * 16), Qhg + (size_t)r * 64 + c * 8);
    }
    cpa_commit();

    // Stage = 128 kv tokens: K 16KB + V 16KB + 512B pos
    auto load_kv = [&](int st, int j0) {
        uint32_t base = sb + AKV_OFF + st * 32768;
        const unsigned short* srcs[2] = {
            Khg + ((size_t)j0 << 6), Vhg + ((size_t)j0 << 6) };
#pragma unroll
        for (int buf = 0; buf < 2; buf++)
#pragma unroll
            for (int i = 0; i < 2; i++) {
                int id = tid + i * 256;      // 0..511 -> 128 rows x 4... no: 2x
            }
#pragma unroll
        for (int buf = 0; buf < 2; buf++)
#pragma unroll
            for (int i = 0; i < 4; i++) {
                int id = tid + i * 256;      // 0..1023
                int r = id >> 3, c = id & 7; // 128 rows x 8 chunks
                cpa16(base + buf * 16384 + SW128(r * 128 + c * 16),
                      srcs[buf] + (size_t)r * 64 + c * 8);
            }
        if (tid < 32)
            cpa16(sb + APOS_OFF + st * 512 + tid * 16, posb + j0 + tid * 4);
    };

    load_kv(0, 0);
    cpa_commit();

    cpa_wait<1>();
    __syncthreads();
    const int a_lr = lane & 15, a_hk = (lane >> 4) << 4;
    uint32_t qfh[4][4];
#pragma unroll
    for (int ks = 0; ks < 4; ks++) {
        int r = wm * 16 + a_lr;
        ldsm4(qfh[ks], sb + AQ_OFF + SW128(r * 128 + ks * 32 + a_hk));
    }

    const int pq0 = posb[i0 + wm * 16 + (lane >> 2)];
    const int pq1 = posb[i0 + wm * 16 + (lane >> 2) + 8];
    const int pqmin = posb[i0];
    const int pqmax = posb[i0 + 127];
    const int jcol = 2 * (lane & 3);

    float m0 = -3e38f, m1 = -3e38f, l0 = 0.f, l1 = 0.f;
    float oacc[8][4];
#pragma unroll
    for (int nt = 0; nt < 8; nt++)
#pragma unroll
        for (int q = 0; q < 4; q++) oacc[nt][q] = 0.f;

    const float CS = 0.18033688011112042f;   // 0.125 * log2(e)

    // Process one 64-token sub-block resident at kb_ (K) / vb (V), pos at pkp.
    auto process = [&](const int* pkp, uint32_t kb_, uint32_t vb) {
        float sacc[8][4];
#pragma unroll
        for (int nt = 0; nt < 8; nt++)
#pragma unroll
            for (int q = 0; q < 4; q++) sacc[nt][q] = 0.f;

#pragma unroll
        for (int ks = 0; ks < 4; ks++) {
            uint32_t kf[4][4];
            const int g = lane >> 3;
            const int krow = (g >> 1) * 8 + (lane & 7);
            const int kchk = ks * 32 + (g & 1) * 16;
#pragma unroll
            for (int call = 0; call < 4; call++) {
                uint32_t off = SW128((call * 16 + krow) * 128 + kchk);
                ldsm4(kf[call], kb_ + off);
            }
#pragma unroll
            for (int nt = 0; nt < 8; nt++) {
                const int c = nt >> 1, hf = (nt & 1) * 2;
                mma16816(sacc[nt], qfh[ks], &kf[c][hf]);
            }
        }

        const bool need_mask = (pkp[63] > pqmin);
        float mx0 = m0, mx1 = m1;
        if (need_mask) {
#pragma unroll
            for (int nt = 0; nt < 8; nt++) {
                int pk0 = pkp[nt * 8 + jcol], pk1 = pkp[nt * 8 + jcol + 1];
                float v0 = (pq0 < pk0) ? -3e38f : sacc[nt][0];
                float v1 = (pq0 < pk1) ? -3e38f : sacc[nt][1];
                float v2 = (pq1 < pk0) ? -3e38f : sacc[nt][2];
                float v3 = (pq1 < pk1) ? -3e38f : sacc[nt][3];
                sacc[nt][0] = v0; sacc[nt][1] = v1;
                sacc[nt][2] = v2; sacc[nt][3] = v3;
                mx0 = fmaxf(mx0, fmaxf(v0, v1));
                mx1 = fmaxf(mx1, fmaxf(v2, v3));
            }
        } else {
#pragma unroll
            for (int nt = 0; nt < 8; nt++) {
                mx0 = fmaxf(mx0, fmaxf(sacc[nt][0], sacc[nt][1]));
                mx1 = fmaxf(mx1, fmaxf(sacc[nt][2], sacc[nt][3]));
            }
        }
        mx0 = fmaxf(mx0, __shfl_xor_sync(0xffffffffu, mx0, 1));
        mx0 = fmaxf(mx0, __shfl_xor_sync(0xffffffffu, mx0, 2));
        mx1 = fmaxf(mx1, __shfl_xor_sync(0xffffffffu, mx1, 1));
        mx1 = fmaxf(mx1, __shfl_xor_sync(0xffffffffu, mx1, 2));
        float al0 = exp2f((m0 - mx0) * CS), al1 = exp2f((m1 - mx1) * CS);
        m0 = mx0; m1 = mx1;
        const float c0 = -mx0 * CS, c1 = -mx1 * CS;

        float s0 = 0.f, s1 = 0.f;
#pragma unroll
        for (int nt = 0; nt < 8; nt++) {
            float p0 = exp2f(fmaf(sacc[nt][0], CS, c0));
            float p1 = exp2f(fmaf(sacc[nt][1], CS, c0));
            float p2 = exp2f(fmaf(sacc[nt][2], CS, c1));
            float p3 = exp2f(fmaf(sacc[nt][3], CS, c1));
            sacc[nt][0] = p0; sacc[nt][1] = p1;
            sacc[nt][2] = p2; sacc[nt][3] = p3;
            s0 += p0 + p1; s1 += p2 + p3;
        }
        s0 += __shfl_xor_sync(0xffffffffu, s0, 1);
        s0 += __shfl_xor_sync(0xffffffffu, s0, 2);
        s1 += __shfl_xor_sync(0xffffffffu, s1, 1);
        s1 += __shfl_xor_sync(0xffffffffu, s1, 2);
        l0 = l0 * al0 + s0;
        l1 = l1 * al1 + s1;

        // Warp-uniform rescale skip: no lane saw a new max -> alphas all 1.0
        bool up = (al0 != 1.f) | (al1 != 1.f);
        if (__any_sync(0xffffffffu, up)) {
#pragma unroll
            for (int nt = 0; nt < 8; nt++) {
                oacc[nt][0] *= al0; oacc[nt][1] *= al0;
                oacc[nt][2] *= al1; oacc[nt][3] *= al1;
            }
        }

#pragma unroll
        for (int kt = 0; kt < 4; kt++) {
            uint32_t ph[4];
#pragma unroll
            for (int q = 0; q < 4; q++) {
                const float* src = (q < 2) ? sacc[2 * kt] : sacc[2 * kt + 1];
                float a = src[(q & 1) * 2], c = src[(q & 1) * 2 + 1];
                __half ha = __float2half_rn(a), hc = __float2half_rn(c);
                ph[q] = (uint32_t)reinterpret_cast<unsigned short&>(ha) |
                        ((uint32_t)reinterpret_cast<unsigned short&>(hc) << 16);
            }
            uint32_t vf[4][4];
#pragma unroll
            for (int call = 0; call < 4; call++) {
                uint32_t off = SW128((kt * 16 + a_lr) * 128 + call * 32 + a_hk);
                ldsm4t(vf[call], vb + off);
            }
#pragma unroll
            for (int nt = 0; nt < 8; nt++) {
                const int c = nt >> 1, hf = (nt & 1) * 2;
                mma16816(oacc[nt], ph, &vf[c][hf]);
            }
        }
    };

    int jb = 0, st = 0;
    for (;;) {
        int next = jb + 128;
        bool hn = (next < Tn) && (posb[next] <= pqmax);

        cpa_wait<0>();          // current 128-token stage fully resident
        __syncthreads();        // seals last iter's reads of stage st^1
        if (hn) { load_kv(st ^ 1, next); cpa_commit(); }

        const uint32_t kvb = sb + AKV_OFF + st * 32768;
        const int* pkps = (const int*)(am + APOS_OFF + st * 512);

        process(pkps, kvb, kvb + 16384);
        if (pkps[64] <= pqmax)
            process(pkps + 64, kvb + 8192, kvb + 16384 + 8192);

        if (!hn) break;
        jb = next; st ^= 1;
    }

    // Epilogue: normalize, write single fp16 to ga_h
    float inv0 = 1.f / l0, inv1 = 1.f / l1;
    int t0r = i0 + wm * 16 + (lane >> 2);
#pragma unroll
    for (int nt = 0; nt < 8; nt++) {
        int col = h * 64 + nt * 8 + jcol;
#pragma unroll
        for (int half = 0; half < 2; half++) {
            int t = t0r + half * 8;
            float inv = half ? inv1 : inv0;
            float v0 = oacc[nt][half * 2] * inv;
            float v1 = oacc[nt][half * 2 + 1] * inv;
            __half h0 = __float2half_rn(v0), h1 = __float2half_rn(v1);
            size_t idx = ((size_t)b * Tn + t) * Dn + col;
            *(uint32_t*)&ga_h[idx] =
                (uint32_t)reinterpret_cast<unsigned short&>(h0) |
                ((uint32_t)reinterpret_cast<unsigned short&>(h1) << 16);
        }
    }
}

// ---------------------------------------------------------------------------
extern "C" void kernel_launch(void* const* d_in, const int* in_sizes, int n_in,
                              void* d_out, int out_size)
{
    const float* x   = (const float*)d_in[0];
    const int*   pos = (const int*)d_in[1];
    const float* Wq  = (const float*)d_in[2];
    const float* Wo  = (const float*)d_in[3];
    float* out = (float*)d_out;

    unsigned short *p_xh, *p_wq, *p_wo, *p_gah;
    cudaGetSymbolAddress((void**)&p_xh,  xa_h);
    cudaGetSymbolAddress((void**)&p_wq,  wq_h);
    cudaGetSymbolAddress((void**)&p_wo,  wo_h);
    cudaGetSymbolAddress((void**)&p_gah, ga_h);

    const int GEMM_SMEM = STAGES * STG_BYTES;   // 98304

    // 0) fused fp16 conversions (x, Wqkv, Wout in one launch)
    int nbx  = (Bn * Tn * Dn) / 4 / 256;     // 2048 blocks
    int nbwq = (3 * Dn * Dn) / 4 / 256;      // 3072 blocks
    int nbwo = (Dn * Dn) / 4 / 256;          // 1024 blocks
    conv_fused_kernel<<<nbx + nbwq + nbwo, 256>>>(x, p_xh, Wq, p_wq, Wo, p_wo,
                                                  nbx, nbwq, nbwo);

    // 1) QKV projection -> qkvh
    cudaFuncSetAttribute(tc_gemm<0, 3072>,
                         cudaFuncAttributeMaxDynamicSharedMemorySize, GEMM_SMEM);
    tc_gemm<0, 3072><<<dim3(24, 64), 256, GEMM_SMEM>>>(p_xh, p_wq, nullptr);

    // 2) tensor-core flash attention (128 q-rows / block) -> ga_h
    cudaFuncSetAttribute(attn_mma,
                         cudaFuncAttributeMaxDynamicSharedMemorySize, ATTN_SMEM_SZ);
    attn_mma<<<dim3(Tn / 128, Bn * Hn), 256, ATTN_SMEM_SZ>>>(pos);

    // 3) output projection -> d_out
    cudaFuncSetAttribute(tc_gemm<1, 1024>,
                         cudaFuncAttributeMaxDynamicSharedMemorySize, GEMM_SMEM);
    tc_gemm<1, 1024><<<dim3(8, 64), 256, GEMM_SMEM>>>(p_gah, p_wo, out);
}

// round 14
// speedup vs baseline: 1.0140x; 1.0140x over previous
#include <cuda_runtime.h>
#include <cuda_fp16.h>
#include <math.h>
#include <stdint.h>

// Problem constants
#define Bn 4
#define Tn 2048
#define Dn 1024
#define Hn 16
#define HDn 64
#define QKV_STRIDE (Bn * Hn * Tn * HDn)   // 8388608 elems per q/k/v

// ---------------------------------------------------------------------------
// Device scratch (no cudaMalloc allowed).  All u16 = fp16 bits.
// ---------------------------------------------------------------------------
__device__ unsigned short qkvh[3ull * QKV_STRIDE];      // [3][B][H][T][HD] fp16
__device__ unsigned short xa_h[(size_t)Bn * Tn * Dn];   // x fp16 [8192][1024]
__device__ unsigned short wq_h[(size_t)3 * Dn * Dn];    // Wqkv fp16 (native K-major)
__device__ unsigned short wo_h[(size_t)Dn * Dn];        // Wout fp16
__device__ unsigned short ga_h[(size_t)Bn * Tn * Dn];   // attention out fp16

// ---------------------------------------------------------------------------
// PTX helpers (non-arch-suffixed; valid on plain sm_103 target)
// ---------------------------------------------------------------------------
__device__ __forceinline__ uint32_t s2u(const void* p) {
    uint32_t a;
    asm("{ .reg .u64 t; cvta.to.shared.u64 t, %1; cvt.u32.u64 %0, t; }"
        : "=r"(a) : "l"(p));
    return a;
}
__device__ __forceinline__ void cpa16(uint32_t d, const void* s) {
    asm volatile("cp.async.cg.shared.global [%0], [%1], 16;"
                 :: "r"(d), "l"(s) : "memory");
}
__device__ __forceinline__ void cpa_commit() {
    asm volatile("cp.async.commit_group;" ::: "memory");
}
template<int N>
__device__ __forceinline__ void cpa_wait() {
    asm volatile("cp.async.wait_group %0;" :: "n"(N) : "memory");
}
__device__ __forceinline__ void ldsm4(uint32_t* r, uint32_t a) {
    asm volatile("ldmatrix.sync.aligned.m8n8.x4.shared.b16 {%0,%1,%2,%3}, [%4];"
        : "=r"(r[0]), "=r"(r[1]), "=r"(r[2]), "=r"(r[3]) : "r"(a));
}
__device__ __forceinline__ void ldsm4t(uint32_t* r, uint32_t a) {
    asm volatile("ldmatrix.sync.aligned.m8n8.x4.trans.shared.b16 {%0,%1,%2,%3}, [%4];"
        : "=r"(r[0]), "=r"(r[1]), "=r"(r[2]), "=r"(r[3]) : "r"(a));
}
__device__ __forceinline__ void mma16816(float* d, const uint32_t* a, const uint32_t* b) {
    asm volatile(
        "mma.sync.aligned.m16n8k16.row.col.f32.f16.f16.f32 "
        "{%0,%1,%2,%3}, {%4,%5,%6,%7}, {%8,%9}, {%0,%1,%2,%3};"
        : "+f"(d[0]), "+f"(d[1]), "+f"(d[2]), "+f"(d[3])
        : "r"(a[0]), "r"(a[1]), "r"(a[2]), "r"(a[3]), "r"(b[0]), "r"(b[1]));
}

// Swizzles
#define SWB(o) ((o) ^ ((((o) >> 8) & 7) << 4))   // 256B rows (GEMM B buf)
#define SW128(o) ((o) ^ ((((o) >> 7) & 7) << 4)) // 128B rows (GEMM A buf + attention)

// fp32 -> single fp16, fused over the three source arrays
__global__ __launch_bounds__(256)
void conv_fused_kernel(const float* __restrict__ x, unsigned short* __restrict__ xo,
                       const float* __restrict__ wq, unsigned short* __restrict__ wqo,
                       const float* __restrict__ wo, unsigned short* __restrict__ woo,
                       int nbx, int nbwq, int nbwo)
{
    const float* src;
    unsigned short* dst;
    int blk = blockIdx.x;
    if (blk < nbx) { src = x; dst = xo; }
    else if (blk < nbx + nbwq) { src = wq; dst = wqo; blk -= nbx; }
    else { src = wo; dst = woo; blk -= nbx + nbwq; }
    int i = blk * 256 + threadIdx.x;
    float4 v = ((const float4*)src)[i];
    __half a = __float2half_rn(v.x), b = __float2half_rn(v.y);
    __half c = __float2half_rn(v.z), d = __float2half_rn(v.w);
    ushort4 h;
    h.x = reinterpret_cast<unsigned short&>(a);
    h.y = reinterpret_cast<unsigned short&>(b);
    h.z = reinterpret_cast<unsigned short&>(c);
    h.w = reinterpret_cast<unsigned short&>(d);
    ((ushort4*)dst)[i] = h;
}

// ---------------------------------------------------------------------------
// Single-term fp16 GEMM via mma.sync: D[8192][NN] = Ah[8192][1024] @ Bh[1024][NN]
// CTA tile = 128 x (WNT*16); warp tile 32 x (WNT*8); 8 warps (4m x 2n).
// BK=64, 3-stage cp.async pipeline, one sync per k-block, 2 CTAs/SM.
// WNT=6 (96-wide, GEMM1: fine grid vs wave quantization), WNT=8 (128-wide).
// B rows stored padded to 256B so SWB/ldsm.t addressing is unchanged.
// MODE 0: fp16 scatter into qkvh.  MODE 1: fp32 write.
// ---------------------------------------------------------------------------
#define BK 64
#define NKB2 16                        // 1024 / 64
#define STAGES 3
#define ABUF 16384                     // 128 rows x 64 fp16 (128B rows)
#define BBUF 16384                     // 64 rows x 256B (padded)
#define STG_BYTES (ABUF + BBUF)        // 32768

template<int MODE, int NN, int WNT>
__global__ __launch_bounds__(256, 2)
void tc_gemm(const unsigned short* __restrict__ Ah,
             const unsigned short* __restrict__ Bh, float* __restrict__ Cout)
{
    extern __shared__ __align__(1024) unsigned char gsm[];
    const uint32_t sbase = s2u(gsm);
    const int tid = threadIdx.x;
    const int lane = tid & 31, wid = tid >> 5;
    const int wm = wid & 3, wn = wid >> 2;
    const int bm = blockIdx.y * 128, bn = blockIdx.x * (WNT * 16);

    const unsigned short* Abase = Ah + (size_t)bm * 1024;
    const unsigned short* Bbase = Bh + bn;

    constexpr int BCH = 2 * WNT;                 // 16B chunks per B row
    constexpr int BCHUNKS = 64 * BCH;            // total B chunks per stage

    auto load_stage = [&](int st, int kb) {
        uint32_t sb = sbase + st * STG_BYTES;
#pragma unroll
        for (int i = 0; i < 4; i++) {
            int id = i * 256 + tid;
            int r = id >> 3, c = id & 7;
            cpa16(sb + SW128(r * 128 + c * 16),
                  Abase + (size_t)r * 1024 + kb * BK + c * 8);
        }
#pragma unroll
        for (int i = 0; i < BCHUNKS / 256; i++) {
            int id = i * 256 + tid;
            int rk = id / BCH, cc = id % BCH;
            cpa16(sb + ABUF + SWB(rk * 256 + cc * 16),
                  Bbase + (size_t)(kb * BK + rk) * NN + cc * 8);
        }
    };

    float acc[2][WNT][4];
#pragma unroll
    for (int mt = 0; mt < 2; mt++)
#pragma unroll
        for (int nt = 0; nt < WNT; nt++)
#pragma unroll
            for (int q = 0; q < 4; q++) acc[mt][nt][q] = 0.f;

    load_stage(0, 0); cpa_commit();
    load_stage(1, 1); cpa_commit();

    const int a_lr = lane & 15;
    const int a_hk = (lane >> 4) << 4;

    for (int kb = 0; kb < NKB2; kb++) {
        const int cur = kb % STAGES;
        cpa_wait<1>();
        __syncthreads();
        if (kb + 2 < NKB2) load_stage((kb + 2) % STAGES, kb + 2);
        cpa_commit();

        uint32_t sb = sbase + cur * STG_BYTES;
#pragma unroll
        for (int ks = 0; ks < 4; ks++) {
            uint32_t afr[2][4];
#pragma unroll
            for (int mt = 0; mt < 2; mt++) {
                int r = wm * 32 + mt * 16 + a_lr;
                ldsm4(afr[mt], sb + SW128(r * 128 + ks * 32 + a_hk));
            }
            uint32_t bfr[WNT][2];
#pragma unroll
            for (int nt2 = 0; nt2 < WNT / 2; nt2++) {
                int kk = ks * 16 + a_lr;
                int nb = wn * (WNT * 16) + nt2 * 32 + a_hk;   // bytes
                uint32_t t[4];
                ldsm4t(t, sb + ABUF + SWB(kk * 256 + nb));
                bfr[nt2 * 2][0] = t[0]; bfr[nt2 * 2][1] = t[1];
                bfr[nt2 * 2 + 1][0] = t[2]; bfr[nt2 * 2 + 1][1] = t[3];
            }
#pragma unroll
            for (int mt = 0; mt < 2; mt++)
#pragma unroll
                for (int nt = 0; nt < WNT; nt++)
                    mma16816(acc[mt][nt], afr[mt], bfr[nt]);
        }
    }

    const int gid = lane >> 2, tg = lane & 3;
#pragma unroll
    for (int mt = 0; mt < 2; mt++)
#pragma unroll
        for (int nt = 0; nt < WNT; nt++) {
            int row0 = bm + wm * 32 + mt * 16 + gid;
            int col = bn + wn * (WNT * 8) + nt * 8 + tg * 2;
#pragma unroll
            for (int half = 0; half < 2; half++) {
                int row = row0 + half * 8;
                float v0 = acc[mt][nt][half * 2], v1 = acc[mt][nt][half * 2 + 1];
                if (MODE == 0) {
                    int s = col >> 10, h = (col >> 6) & 15, d = col & 63;
                    int b = row >> 11, t = row & 2047;
                    size_t idx = (size_t)s * QKV_STRIDE +
                                 (((size_t)(b * Hn + h) * Tn + t) << 6) + d;
                    __half h0 = __float2half_rn(v0), h1 = __float2half_rn(v1);
                    *(uint32_t*)&qkvh[idx] =
                        (uint32_t)reinterpret_cast<unsigned short&>(h0) |
                        ((uint32_t)reinterpret_cast<unsigned short&>(h1) << 16);
                } else {
                    *(float2*)&Cout[(size_t)row * NN + col] = make_float2(v0, v1);
                }
            }
        }
}

// ---------------------------------------------------------------------------
// Tensor-core flash attention, single-term fp16 (fp32 accum) — R12 version.
// 256 threads = 8 warps; 128 q rows per block.  2 CTAs/SM.
// Raw-logit softmax (scale folded into exp), mask-free fast path,
// descending tile order.
// ---------------------------------------------------------------------------
#define AQ_OFF 0                     // Q 16KB (128 rows x 128B)
#define AKV_OFF 16384                // 2 stages x (K 8KB + V 8KB)
#define APOS_OFF (16384 + 32768)     // 49152
#define ATTN_SMEM_SZ (16384 + 32768 + 512)

__global__ __launch_bounds__(256, 2)
void attn_mma(const int* __restrict__ pos)
{
    extern __shared__ __align__(1024) unsigned char am[];
    const uint32_t sb = s2u(am);
    const int tid = threadIdx.x, lane = tid & 31, wm = tid >> 5;   // wm 0..7
    const int b = blockIdx.y >> 4, h = blockIdx.y & 15;
    const int i0 = (15 - blockIdx.x) * 128;    // heavy tiles scheduled first

    const size_t bh_off = ((size_t)(b * Hn + h) * Tn) << 6;
    const unsigned short* Qhg = qkvh + bh_off + ((size_t)i0 << 6);
    const unsigned short* Khg = qkvh + (size_t)QKV_STRIDE + bh_off;
    const unsigned short* Vhg = qkvh + 2ull * QKV_STRIDE + bh_off;
    const int* posb = pos + b * Tn;

    // Q tile (128 rows) -> smem: 1024 16B-chunks
#pragma unroll
    for (int i = 0; i < 4; i++) {
        int id = tid + i * 256;
        int r = id >> 3, c = id & 7;
        cpa16(sb + AQ_OFF + SW128(r * 128 + c * 16), Qhg + (size_t)r * 64 + c * 8);
    }
    cpa_commit();

    auto load_kv = [&](int st, int j0) {
        uint32_t base = sb + AKV_OFF + st * 16384;
        const unsigned short* srcs[2] = {
            Khg + ((size_t)j0 << 6), Vhg + ((size_t)j0 << 6) };
#pragma unroll
        for (int buf = 0; buf < 2; buf++)
#pragma unroll
            for (int i = 0; i < 2; i++) {
                int id = tid + i * 256;      // 0..511
                int r = id >> 3, c = id & 7;
                cpa16(base + buf * 8192 + SW128(r * 128 + c * 16),
                      srcs[buf] + (size_t)r * 64 + c * 8);
            }
        if (tid < 16)
            cpa16(sb + APOS_OFF + st * 256 + tid * 16, posb + j0 + tid * 4);
    };

    load_kv(0, 0);
    cpa_commit();

    cpa_wait<1>();
    __syncthreads();
    const int a_lr = lane & 15, a_hk = (lane >> 4) << 4;
    uint32_t qfh[4][4];
#pragma unroll
    for (int ks = 0; ks < 4; ks++) {
        int r = wm * 16 + a_lr;
        ldsm4(qfh[ks], sb + AQ_OFF + SW128(r * 128 + ks * 32 + a_hk));
    }

    const int pq0 = posb[i0 + wm * 16 + (lane >> 2)];
    const int pq1 = posb[i0 + wm * 16 + (lane >> 2) + 8];
    const int pqmin = posb[i0];
    const int pqmax = posb[i0 + 127];
    const int jcol = 2 * (lane & 3);

    float m0 = -3e38f, m1 = -3e38f, l0 = 0.f, l1 = 0.f;
    float oacc[8][4];
#pragma unroll
    for (int nt = 0; nt < 8; nt++)
#pragma unroll
        for (int q = 0; q < 4; q++) oacc[nt][q] = 0.f;

    const float CS = 0.18033688011112042f;   // 0.125 * log2(e)

    int jb = 0, st = 0;
    for (;;) {
        int next = jb + 64;
        bool hn = (next < Tn) && (posb[next] <= pqmax);

        cpa_wait<0>();          // current stage fully resident
        __syncthreads();        // seals last iter's reads of stage st^1
        if (hn) { load_kv(st ^ 1, next); cpa_commit(); }

        const uint32_t kb_ = sb + AKV_OFF + st * 16384;
        const int* pkp = (const int*)(am + APOS_OFF + st * 256);

        float sacc[8][4];
#pragma unroll
        for (int nt = 0; nt < 8; nt++)
#pragma unroll
            for (int q = 0; q < 4; q++) sacc[nt][q] = 0.f;

#pragma unroll
        for (int ks = 0; ks < 4; ks++) {
            uint32_t kf[4][4];
            const int g = lane >> 3;
            const int krow = (g >> 1) * 8 + (lane & 7);
            const int kchk = ks * 32 + (g & 1) * 16;
#pragma unroll
            for (int call = 0; call < 4; call++) {
                uint32_t off = SW128((call * 16 + krow) * 128 + kchk);
                ldsm4(kf[call], kb_ + off);
            }
#pragma unroll
            for (int nt = 0; nt < 8; nt++) {
                const int c = nt >> 1, hf = (nt & 1) * 2;
                mma16816(sacc[nt], qfh[ks], &kf[c][hf]);
            }
        }

        // ---- online softmax on RAW logits; scale folded into exp ----
        const bool need_mask = (pkp[63] > pqmin);
        float mx0 = m0, mx1 = m1;
        if (need_mask) {
#pragma unroll
            for (int nt = 0; nt < 8; nt++) {
                int pk0 = pkp[nt * 8 + jcol], pk1 = pkp[nt * 8 + jcol + 1];
                float v0 = (pq0 < pk0) ? -3e38f : sacc[nt][0];
                float v1 = (pq0 < pk1) ? -3e38f : sacc[nt][1];
                float v2 = (pq1 < pk0) ? -3e38f : sacc[nt][2];
                float v3 = (pq1 < pk1) ? -3e38f : sacc[nt][3];
                sacc[nt][0] = v0; sacc[nt][1] = v1;
                sacc[nt][2] = v2; sacc[nt][3] = v3;
                mx0 = fmaxf(mx0, fmaxf(v0, v1));
                mx1 = fmaxf(mx1, fmaxf(v2, v3));
            }
        } else {
#pragma unroll
            for (int nt = 0; nt < 8; nt++) {
                mx0 = fmaxf(mx0, fmaxf(sacc[nt][0], sacc[nt][1]));
                mx1 = fmaxf(mx1, fmaxf(sacc[nt][2], sacc[nt][3]));
            }
        }
        mx0 = fmaxf(mx0, __shfl_xor_sync(0xffffffffu, mx0, 1));
        mx0 = fmaxf(mx0, __shfl_xor_sync(0xffffffffu, mx0, 2));
        mx1 = fmaxf(mx1, __shfl_xor_sync(0xffffffffu, mx1, 1));
        mx1 = fmaxf(mx1, __shfl_xor_sync(0xffffffffu, mx1, 2));
        float al0 = exp2f((m0 - mx0) * CS), al1 = exp2f((m1 - mx1) * CS);
        m0 = mx0; m1 = mx1;
        const float c0 = -mx0 * CS, c1 = -mx1 * CS;

        float s0 = 0.f, s1 = 0.f;
#pragma unroll
        for (int nt = 0; nt < 8; nt++) {
            float p0 = exp2f(fmaf(sacc[nt][0], CS, c0));
            float p1 = exp2f(fmaf(sacc[nt][1], CS, c0));
            float p2 = exp2f(fmaf(sacc[nt][2], CS, c1));
            float p3 = exp2f(fmaf(sacc[nt][3], CS, c1));
            sacc[nt][0] = p0; sacc[nt][1] = p1;
            sacc[nt][2] = p2; sacc[nt][3] = p3;
            s0 += p0 + p1; s1 += p2 + p3;
        }
        s0 += __shfl_xor_sync(0xffffffffu, s0, 1);
        s0 += __shfl_xor_sync(0xffffffffu, s0, 2);
        s1 += __shfl_xor_sync(0xffffffffu, s1, 1);
        s1 += __shfl_xor_sync(0xffffffffu, s1, 2);
        l0 = l0 * al0 + s0;
        l1 = l1 * al1 + s1;
#pragma unroll
        for (int nt = 0; nt < 8; nt++) {
            oacc[nt][0] *= al0; oacc[nt][1] *= al0;
            oacc[nt][2] *= al1; oacc[nt][3] *= al1;
        }

        const uint32_t vb = kb_ + 8192;
#pragma unroll
        for (int kt = 0; kt < 4; kt++) {
            uint32_t ph[4];
#pragma unroll
            for (int q = 0; q < 4; q++) {
                const float* src = (q < 2) ? sacc[2 * kt] : sacc[2 * kt + 1];
                float a = src[(q & 1) * 2], c = src[(q & 1) * 2 + 1];
                __half ha = __float2half_rn(a), hc = __float2half_rn(c);
                ph[q] = (uint32_t)reinterpret_cast<unsigned short&>(ha) |
                        ((uint32_t)reinterpret_cast<unsigned short&>(hc) << 16);
            }
            uint32_t vf[4][4];
#pragma unroll
            for (int call = 0; call < 4; call++) {
                uint32_t off = SW128((kt * 16 + a_lr) * 128 + call * 32 + a_hk);
                ldsm4t(vf[call], vb + off);
            }
#pragma unroll
            for (int nt = 0; nt < 8; nt++) {
                const int c = nt >> 1, hf = (nt & 1) * 2;
                mma16816(oacc[nt], ph, &vf[c][hf]);
            }
        }

        if (!hn) break;
        jb = next; st ^= 1;
    }

    // Epilogue: normalize, write single fp16 to ga_h
    float inv0 = 1.f / l0, inv1 = 1.f / l1;
    int t0r = i0 + wm * 16 + (lane >> 2);
#pragma unroll
    for (int nt = 0; nt < 8; nt++) {
        int col = h * 64 + nt * 8 + jcol;
#pragma unroll
        for (int half = 0; half < 2; half++) {
            int t = t0r + half * 8;
            float inv = half ? inv1 : inv0;
            float v0 = oacc[nt][half * 2] * inv;
            float v1 = oacc[nt][half * 2 + 1] * inv;
            __half h0 = __float2half_rn(v0), h1 = __float2half_rn(v1);
            size_t idx = ((size_t)b * Tn + t) * Dn + col;
            *(uint32_t*)&ga_h[idx] =
                (uint32_t)reinterpret_cast<unsigned short&>(h0) |
                ((uint32_t)reinterpret_cast<unsigned short&>(h1) << 16);
        }
    }
}

// ---------------------------------------------------------------------------
extern "C" void kernel_launch(void* const* d_in, const int* in_sizes, int n_in,
                              void* d_out, int out_size)
{
    const float* x   = (const float*)d_in[0];
    const int*   pos = (const int*)d_in[1];
    const float* Wq  = (const float*)d_in[2];
    const float* Wo  = (const float*)d_in[3];
    float* out = (float*)d_out;

    unsigned short *p_xh, *p_wq, *p_wo, *p_gah;
    cudaGetSymbolAddress((void**)&p_xh,  xa_h);
    cudaGetSymbolAddress((void**)&p_wq,  wq_h);
    cudaGetSymbolAddress((void**)&p_wo,  wo_h);
    cudaGetSymbolAddress((void**)&p_gah, ga_h);

    const int GEMM_SMEM = STAGES * STG_BYTES;   // 98304

    // 0) fused fp16 conversions (x, Wqkv, Wout in one launch)
    int nbx  = (Bn * Tn * Dn) / 4 / 256;     // 2048 blocks
    int nbwq = (3 * Dn * Dn) / 4 / 256;      // 3072 blocks
    int nbwo = (Dn * Dn) / 4 / 256;          // 1024 blocks
    conv_fused_kernel<<<nbx + nbwq + nbwo, 256>>>(x, p_xh, Wq, p_wq, Wo, p_wo,
                                                  nbx, nbwq, nbwo);

    // 1) QKV projection -> qkvh   (96-wide N tiles: grid 32x64 = 2048 CTAs)
    cudaFuncSetAttribute(tc_gemm<0, 3072, 6>,
                         cudaFuncAttributeMaxDynamicSharedMemorySize, GEMM_SMEM);
    tc_gemm<0, 3072, 6><<<dim3(32, 64), 256, GEMM_SMEM>>>(p_xh, p_wq, nullptr);

    // 2) tensor-core flash attention (128 q-rows / block) -> ga_h
    cudaFuncSetAttribute(attn_mma,
                         cudaFuncAttributeMaxDynamicSharedMemorySize, ATTN_SMEM_SZ);
    attn_mma<<<dim3(Tn / 128, Bn * Hn), 256, ATTN_SMEM_SZ>>>(pos);

    // 3) output projection -> d_out  (128-wide N tiles)
    cudaFuncSetAttribute(tc_gemm<1, 1024, 8>,
                         cudaFuncAttributeMaxDynamicSharedMemorySize, GEMM_SMEM);
    tc_gemm<1, 1024, 8><<<dim3(8, 64), 256, GEMM_SMEM>>>(p_gah, p_wo, out);
}

// round 15
// speedup vs baseline: 1.0157x; 1.0016x over previous
#include <cuda_runtime.h>
#include <cuda_fp16.h>
#include <math.h>
#include <stdint.h>

// Problem constants
#define Bn 4
#define Tn 2048
#define Dn 1024
#define Hn 16
#define HDn 64
#define QKV_STRIDE (Bn * Hn * Tn * HDn)   // 8388608 elems per q/k/v

// ---------------------------------------------------------------------------
// Device scratch (no cudaMalloc allowed).  All u16 = fp16 bits.
// ---------------------------------------------------------------------------
__device__ unsigned short qkvh[3ull * QKV_STRIDE];      // [3][B][H][T][HD] fp16
__device__ unsigned short xa_h[(size_t)Bn * Tn * Dn];   // x fp16 [8192][1024]
__device__ unsigned short wq_h[(size_t)3 * Dn * Dn];    // Wqkv fp16 (native K-major)
__device__ unsigned short wo_h[(size_t)Dn * Dn];        // Wout fp16
__device__ unsigned short ga_h[(size_t)Bn * Tn * Dn];   // attention out fp16

// ---------------------------------------------------------------------------
// PTX helpers (non-arch-suffixed; valid on plain sm_103 target)
// ---------------------------------------------------------------------------
__device__ __forceinline__ uint32_t s2u(const void* p) {
    uint32_t a;
    asm("{ .reg .u64 t; cvta.to.shared.u64 t, %1; cvt.u32.u64 %0, t; }"
        : "=r"(a) : "l"(p));
    return a;
}
__device__ __forceinline__ void cpa16(uint32_t d, const void* s) {
    asm volatile("cp.async.cg.shared.global [%0], [%1], 16;"
                 :: "r"(d), "l"(s) : "memory");
}
__device__ __forceinline__ void cpa_commit() {
    asm volatile("cp.async.commit_group;" ::: "memory");
}
template<int N>
__device__ __forceinline__ void cpa_wait() {
    asm volatile("cp.async.wait_group %0;" :: "n"(N) : "memory");
}
__device__ __forceinline__ void ldsm4(uint32_t* r, uint32_t a) {
    asm volatile("ldmatrix.sync.aligned.m8n8.x4.shared.b16 {%0,%1,%2,%3}, [%4];"
        : "=r"(r[0]), "=r"(r[1]), "=r"(r[2]), "=r"(r[3]) : "r"(a));
}
__device__ __forceinline__ void ldsm4t(uint32_t* r, uint32_t a) {
    asm volatile("ldmatrix.sync.aligned.m8n8.x4.trans.shared.b16 {%0,%1,%2,%3}, [%4];"
        : "=r"(r[0]), "=r"(r[1]), "=r"(r[2]), "=r"(r[3]) : "r"(a));
}
__device__ __forceinline__ void mma16816(float* d, const uint32_t* a, const uint32_t* b) {
    asm volatile(
        "mma.sync.aligned.m16n8k16.row.col.f32.f16.f16.f32 "
        "{%0,%1,%2,%3}, {%4,%5,%6,%7}, {%8,%9}, {%0,%1,%2,%3};"
        : "+f"(d[0]), "+f"(d[1]), "+f"(d[2]), "+f"(d[3])
        : "r"(a[0]), "r"(a[1]), "r"(a[2]), "r"(a[3]), "r"(b[0]), "r"(b[1]));
}
// Guaranteed single-MUFU exp2 (avoids precise libdevice path when fast-math off)
__device__ __forceinline__ float ex2(float x) {
    float r;
    asm("ex2.approx.ftz.f32 %0, %1;" : "=f"(r) : "f"(x));
    return r;
}

// Swizzles
#define SWB(o) ((o) ^ ((((o) >> 8) & 7) << 4))   // 256B rows (GEMM B buf)
#define SW128(o) ((o) ^ ((((o) >> 7) & 7) << 4)) // 128B rows (GEMM A buf + attention)

// fp32 -> single fp16, fused over the three source arrays
__global__ __launch_bounds__(256)
void conv_fused_kernel(const float* __restrict__ x, unsigned short* __restrict__ xo,
                       const float* __restrict__ wq, unsigned short* __restrict__ wqo,
                       const float* __restrict__ wo, unsigned short* __restrict__ woo,
                       int nbx, int nbwq, int nbwo)
{
    const float* src;
    unsigned short* dst;
    int blk = blockIdx.x;
    if (blk < nbx) { src = x; dst = xo; }
    else if (blk < nbx + nbwq) { src = wq; dst = wqo; blk -= nbx; }
    else { src = wo; dst = woo; blk -= nbx + nbwq; }
    int i = blk * 256 + threadIdx.x;
    float4 v = ((const float4*)src)[i];
    __half a = __float2half_rn(v.x), b = __float2half_rn(v.y);
    __half c = __float2half_rn(v.z), d = __float2half_rn(v.w);
    ushort4 h;
    h.x = reinterpret_cast<unsigned short&>(a);
    h.y = reinterpret_cast<unsigned short&>(b);
    h.z = reinterpret_cast<unsigned short&>(c);
    h.w = reinterpret_cast<unsigned short&>(d);
    ((ushort4*)dst)[i] = h;
}

// ---------------------------------------------------------------------------
// Single-term fp16 GEMM via mma.sync: D[8192][NN] = Ah[8192][1024] @ Bh[1024][NN]
// 128x128 CTA tile, BK=64, 3-stage cp.async pipeline (32KB/stage), 8 warps
// (4m x 2n), warp tile 32x64, 64 MMAs per k-block, one sync per k-block.
// 2 CTAs/SM enforced.  MODE 0: fp16 scatter into qkvh.  MODE 1: fp32 write.
// ---------------------------------------------------------------------------
#define BK 64
#define NKB2 16                        // 1024 / 64
#define STAGES 3
#define ABUF 16384                     // 128 rows x 64 fp16 (128B rows)
#define BBUF 16384                     // 64 rows x 128 fp16 (256B rows)
#define STG_BYTES (ABUF + BBUF)        // 32768

template<int MODE, int NN>
__global__ __launch_bounds__(256, 2)
void tc_gemm(const unsigned short* __restrict__ Ah,
             const unsigned short* __restrict__ Bh, float* __restrict__ Cout)
{
    extern __shared__ __align__(1024) unsigned char gsm[];
    const uint32_t sbase = s2u(gsm);
    const int tid = threadIdx.x;
    const int lane = tid & 31, wid = tid >> 5;
    const int wm = wid & 3, wn = wid >> 2;
    const int bm = blockIdx.y * 128, bn = blockIdx.x * 128;

    const unsigned short* Abase = Ah + (size_t)bm * 1024;
    const unsigned short* Bbase = Bh + bn;

    auto load_stage = [&](int st, int kb) {
        uint32_t sb = sbase + st * STG_BYTES;
#pragma unroll
        for (int i = 0; i < 4; i++) {
            int id = i * 256 + tid;
            int r = id >> 3, c = id & 7;
            cpa16(sb + SW128(r * 128 + c * 16),
                  Abase + (size_t)r * 1024 + kb * BK + c * 8);
        }
#pragma unroll
        for (int i = 0; i < 4; i++) {
            int id = i * 256 + tid;
            int rk = id >> 4, cc = id & 15;
            cpa16(sb + ABUF + SWB(rk * 256 + cc * 16),
                  Bbase + (size_t)(kb * BK + rk) * NN + cc * 8);
        }
    };

    float acc[2][8][4];
#pragma unroll
    for (int mt = 0; mt < 2; mt++)
#pragma unroll
        for (int nt = 0; nt < 8; nt++)
#pragma unroll
            for (int q = 0; q < 4; q++) acc[mt][nt][q] = 0.f;

    load_stage(0, 0); cpa_commit();
    load_stage(1, 1); cpa_commit();

    const int a_lr = lane & 15;
    const int a_hk = (lane >> 4) << 4;

    for (int kb = 0; kb < NKB2; kb++) {
        const int cur = kb % STAGES;
        cpa_wait<1>();
        __syncthreads();
        if (kb + 2 < NKB2) load_stage((kb + 2) % STAGES, kb + 2);
        cpa_commit();

        uint32_t sb = sbase + cur * STG_BYTES;
#pragma unroll
        for (int ks = 0; ks < 4; ks++) {
            uint32_t afr[2][4];
#pragma unroll
            for (int mt = 0; mt < 2; mt++) {
                int r = wm * 32 + mt * 16 + a_lr;
                ldsm4(afr[mt], sb + SW128(r * 128 + ks * 32 + a_hk));
            }
            uint32_t bfr[8][2];
#pragma unroll
            for (int nt2 = 0; nt2 < 4; nt2++) {
                int kk = ks * 16 + a_lr;
                int nb = wn * 128 + nt2 * 32 + a_hk;
                uint32_t t[4];
                ldsm4t(t, sb + ABUF + SWB(kk * 256 + nb));
                bfr[nt2 * 2][0] = t[0]; bfr[nt2 * 2][1] = t[1];
                bfr[nt2 * 2 + 1][0] = t[2]; bfr[nt2 * 2 + 1][1] = t[3];
            }
#pragma unroll
            for (int mt = 0; mt < 2; mt++)
#pragma unroll
                for (int nt = 0; nt < 8; nt++)
                    mma16816(acc[mt][nt], afr[mt], bfr[nt]);
        }
    }

    const int gid = lane >> 2, tg = lane & 3;
#pragma unroll
    for (int mt = 0; mt < 2; mt++)
#pragma unroll
        for (int nt = 0; nt < 8; nt++) {
            int row0 = bm + wm * 32 + mt * 16 + gid;
            int col = bn + wn * 64 + nt * 8 + tg * 2;
#pragma unroll
            for (int half = 0; half < 2; half++) {
                int row = row0 + half * 8;
                float v0 = acc[mt][nt][half * 2], v1 = acc[mt][nt][half * 2 + 1];
                if (MODE == 0) {
                    int s = col >> 10, h = (col >> 6) & 15, d = col & 63;
                    int b = row >> 11, t = row & 2047;
                    size_t idx = (size_t)s * QKV_STRIDE +
                                 (((size_t)(b * Hn + h) * Tn + t) << 6) + d;
                    __half h0 = __float2half_rn(v0), h1 = __float2half_rn(v1);
                    *(uint32_t*)&qkvh[idx] =
                        (uint32_t)reinterpret_cast<unsigned short&>(h0) |
                        ((uint32_t)reinterpret_cast<unsigned short&>(h1) << 16);
                } else {
                    *(float2*)&Cout[(size_t)row * NN + col] = make_float2(v0, v1);
                }
            }
        }
}

// ---------------------------------------------------------------------------
// Tensor-core flash attention, single-term fp16 (fp32 accum).
// 256 threads = 8 warps; 128 q rows per block.  2 CTAs/SM.
// Raw-logit softmax with scale folded into a single ex2.approx per element;
// mask-free fast path; descending tile order.
// ---------------------------------------------------------------------------
#define AQ_OFF 0                     // Q 16KB (128 rows x 128B)
#define AKV_OFF 16384                // 2 stages x (K 8KB + V 8KB)
#define APOS_OFF (16384 + 32768)     // 49152
#define ATTN_SMEM_SZ (16384 + 32768 + 512)

__global__ __launch_bounds__(256, 2)
void attn_mma(const int* __restrict__ pos)
{
    extern __shared__ __align__(1024) unsigned char am[];
    const uint32_t sb = s2u(am);
    const int tid = threadIdx.x, lane = tid & 31, wm = tid >> 5;   // wm 0..7
    const int b = blockIdx.y >> 4, h = blockIdx.y & 15;
    const int i0 = (15 - blockIdx.x) * 128;    // heavy tiles scheduled first

    const size_t bh_off = ((size_t)(b * Hn + h) * Tn) << 6;
    const unsigned short* Qhg = qkvh + bh_off + ((size_t)i0 << 6);
    const unsigned short* Khg = qkvh + (size_t)QKV_STRIDE + bh_off;
    const unsigned short* Vhg = qkvh + 2ull * QKV_STRIDE + bh_off;
    const int* posb = pos + b * Tn;

    // Q tile (128 rows) -> smem: 1024 16B-chunks
#pragma unroll
    for (int i = 0; i < 4; i++) {
        int id = tid + i * 256;
        int r = id >> 3, c = id & 7;
        cpa16(sb + AQ_OFF + SW128(r * 128 + c * 16), Qhg + (size_t)r * 64 + c * 8);
    }
    cpa_commit();

    auto load_kv = [&](int st, int j0) {
        uint32_t base = sb + AKV_OFF + st * 16384;
        const unsigned short* srcs[2] = {
            Khg + ((size_t)j0 << 6), Vhg + ((size_t)j0 << 6) };
#pragma unroll
        for (int buf = 0; buf < 2; buf++)
#pragma unroll
            for (int i = 0; i < 2; i++) {
                int id = tid + i * 256;      // 0..511
                int r = id >> 3, c = id & 7;
                cpa16(base + buf * 8192 + SW128(r * 128 + c * 16),
                      srcs[buf] + (size_t)r * 64 + c * 8);
            }
        if (tid < 16)
            cpa16(sb + APOS_OFF + st * 256 + tid * 16, posb + j0 + tid * 4);
    };

    load_kv(0, 0);
    cpa_commit();

    cpa_wait<1>();
    __syncthreads();
    const int a_lr = lane & 15, a_hk = (lane >> 4) << 4;
    uint32_t qfh[4][4];
#pragma unroll
    for (int ks = 0; ks < 4; ks++) {
        int r = wm * 16 + a_lr;
        ldsm4(qfh[ks], sb + AQ_OFF + SW128(r * 128 + ks * 32 + a_hk));
    }

    const int pq0 = posb[i0 + wm * 16 + (lane >> 2)];
    const int pq1 = posb[i0 + wm * 16 + (lane >> 2) + 8];
    const int pqmin = posb[i0];
    const int pqmax = posb[i0 + 127];
    const int jcol = 2 * (lane & 3);

    float m0 = -3e38f, m1 = -3e38f, l0 = 0.f, l1 = 0.f;
    float oacc[8][4];
#pragma unroll
    for (int nt = 0; nt < 8; nt++)
#pragma unroll
        for (int q = 0; q < 4; q++) oacc[nt][q] = 0.f;

    const float CS = 0.18033688011112042f;   // 0.125 * log2(e)

    int jb = 0, st = 0;
    for (;;) {
        int next = jb + 64;
        bool hn = (next < Tn) && (posb[next] <= pqmax);

        cpa_wait<0>();          // current stage fully resident
        __syncthreads();        // seals last iter's reads of stage st^1
        if (hn) { load_kv(st ^ 1, next); cpa_commit(); }

        const uint32_t kb_ = sb + AKV_OFF + st * 16384;
        const int* pkp = (const int*)(am + APOS_OFF + st * 256);

        float sacc[8][4];
#pragma unroll
        for (int nt = 0; nt < 8; nt++)
#pragma unroll
            for (int q = 0; q < 4; q++) sacc[nt][q] = 0.f;

#pragma unroll
        for (int ks = 0; ks < 4; ks++) {
            uint32_t kf[4][4];
            const int g = lane >> 3;
            const int krow = (g >> 1) * 8 + (lane & 7);
            const int kchk = ks * 32 + (g & 1) * 16;
#pragma unroll
            for (int call = 0; call < 4; call++) {
                uint32_t off = SW128((call * 16 + krow) * 128 + kchk);
                ldsm4(kf[call], kb_ + off);
            }
#pragma unroll
            for (int nt = 0; nt < 8; nt++) {
                const int c = nt >> 1, hf = (nt & 1) * 2;
                mma16816(sacc[nt], qfh[ks], &kf[c][hf]);
            }
        }

        // ---- online softmax on RAW logits; scale folded into exp ----
        const bool need_mask = (pkp[63] > pqmin);
        float mx0 = m0, mx1 = m1;
        if (need_mask) {
#pragma unroll
            for (int nt = 0; nt < 8; nt++) {
                int pk0 = pkp[nt * 8 + jcol], pk1 = pkp[nt * 8 + jcol + 1];
                float v0 = (pq0 < pk0) ? -3e38f : sacc[nt][0];
                float v1 = (pq0 < pk1) ? -3e38f : sacc[nt][1];
                float v2 = (pq1 < pk0) ? -3e38f : sacc[nt][2];
                float v3 = (pq1 < pk1) ? -3e38f : sacc[nt][3];
                sacc[nt][0] = v0; sacc[nt][1] = v1;
                sacc[nt][2] = v2; sacc[nt][3] = v3;
                mx0 = fmaxf(mx0, fmaxf(v0, v1));
                mx1 = fmaxf(mx1, fmaxf(v2, v3));
            }
        } else {
#pragma unroll
            for (int nt = 0; nt < 8; nt++) {
                mx0 = fmaxf(mx0, fmaxf(sacc[nt][0], sacc[nt][1]));
                mx1 = fmaxf(mx1, fmaxf(sacc[nt][2], sacc[nt][3]));
            }
        }
        mx0 = fmaxf(mx0, __shfl_xor_sync(0xffffffffu, mx0, 1));
        mx0 = fmaxf(mx0, __shfl_xor_sync(0xffffffffu, mx0, 2));
        mx1 = fmaxf(mx1, __shfl_xor_sync(0xffffffffu, mx1, 1));
        mx1 = fmaxf(mx1, __shfl_xor_sync(0xffffffffu, mx1, 2));
        float al0 = ex2((m0 - mx0) * CS), al1 = ex2((m1 - mx1) * CS);
        m0 = mx0; m1 = mx1;
        const float c0 = -mx0 * CS, c1 = -mx1 * CS;

        float s0 = 0.f, s1 = 0.f;
#pragma unroll
        for (int nt = 0; nt < 8; nt++) {
            float p0 = ex2(fmaf(sacc[nt][0], CS, c0));
            float p1 = ex2(fmaf(sacc[nt][1], CS, c0));
            float p2 = ex2(fmaf(sacc[nt][2], CS, c1));
            float p3 = ex2(fmaf(sacc[nt][3], CS, c1));
            sacc[nt][0] = p0; sacc[nt][1] = p1;
            sacc[nt][2] = p2; sacc[nt][3] = p3;
            s0 += p0 + p1; s1 += p2 + p3;
        }
        s0 += __shfl_xor_sync(0xffffffffu, s0, 1);
        s0 += __shfl_xor_sync(0xffffffffu, s0, 2);
        s1 += __shfl_xor_sync(0xffffffffu, s1, 1);
        s1 += __shfl_xor_sync(0xffffffffu, s1, 2);
        l0 = l0 * al0 + s0;
        l1 = l1 * al1 + s1;
#pragma unroll
        for (int nt = 0; nt < 8; nt++) {
            oacc[nt][0] *= al0; oacc[nt][1] *= al0;
            oacc[nt][2] *= al1; oacc[nt][3] *= al1;
        }

        const uint32_t vb = kb_ + 8192;
#pragma unroll
        for (int kt = 0; kt < 4; kt++) {
            uint32_t ph[4];
#pragma unroll
            for (int q = 0; q < 4; q++) {
                const float* src = (q < 2) ? sacc[2 * kt] : sacc[2 * kt + 1];
                float a = src[(q & 1) * 2], c = src[(q & 1) * 2 + 1];
                __half ha = __float2half_rn(a), hc = __float2half_rn(c);
                ph[q] = (uint32_t)reinterpret_cast<unsigned short&>(ha) |
                        ((uint32_t)reinterpret_cast<unsigned short&>(hc) << 16);
            }
            uint32_t vf[4][4];
#pragma unroll
            for (int call = 0; call < 4; call++) {
                uint32_t off = SW128((kt * 16 + a_lr) * 128 + call * 32 + a_hk);
                ldsm4t(vf[call], vb + off);
            }
#pragma unroll
            for (int nt = 0; nt < 8; nt++) {
                const int c = nt >> 1, hf = (nt & 1) * 2;
                mma16816(oacc[nt], ph, &vf[c][hf]);
            }
        }

        if (!hn) break;
        jb = next; st ^= 1;
    }

    // Epilogue: normalize, write single fp16 to ga_h
    float inv0 = 1.f / l0, inv1 = 1.f / l1;
    int t0r = i0 + wm * 16 + (lane >> 2);
#pragma unroll
    for (int nt = 0; nt < 8; nt++) {
        int col = h * 64 + nt * 8 + jcol;
#pragma unroll
        for (int half = 0; half < 2; half++) {
            int t = t0r + half * 8;
            float inv = half ? inv1 : inv0;
            float v0 = oacc[nt][half * 2] * inv;
            float v1 = oacc[nt][half * 2 + 1] * inv;
            __half h0 = __float2half_rn(v0), h1 = __float2half_rn(v1);
            size_t idx = ((size_t)b * Tn + t) * Dn + col;
            *(uint32_t*)&ga_h[idx] =
                (uint32_t)reinterpret_cast<unsigned short&>(h0) |
                ((uint32_t)reinterpret_cast<unsigned short&>(h1) << 16);
        }
    }
}

// ---------------------------------------------------------------------------
extern "C" void kernel_launch(void* const* d_in, const int* in_sizes, int n_in,
                              void* d_out, int out_size)
{
    const float* x   = (const float*)d_in[0];
    const int*   pos = (const int*)d_in[1];
    const float* Wq  = (const float*)d_in[2];
    const float* Wo  = (const float*)d_in[3];
    float* out = (float*)d_out;

    unsigned short *p_xh, *p_wq, *p_wo, *p_gah;
    cudaGetSymbolAddress((void**)&p_xh,  xa_h);
    cudaGetSymbolAddress((void**)&p_wq,  wq_h);
    cudaGetSymbolAddress((void**)&p_wo,  wo_h);
    cudaGetSymbolAddress((void**)&p_gah, ga_h);

    const int GEMM_SMEM = STAGES * STG_BYTES;   // 98304

    // 0) fused fp16 conversions (x, Wqkv, Wout in one launch)
    int nbx  = (Bn * Tn * Dn) / 4 / 256;     // 2048 blocks
    int nbwq = (3 * Dn * Dn) / 4 / 256;      // 3072 blocks
    int nbwo = (Dn * Dn) / 4 / 256;          // 1024 blocks
    conv_fused_kernel<<<nbx + nbwq + nbwo, 256>>>(x, p_xh, Wq, p_wq, Wo, p_wo,
                                                  nbx, nbwq, nbwo);

    // 1) QKV projection -> qkvh
    cudaFuncSetAttribute(tc_gemm<0, 3072>,
                         cudaFuncAttributeMaxDynamicSharedMemorySize, GEMM_SMEM);
    tc_gemm<0, 3072><<<dim3(24, 64), 256, GEMM_SMEM>>>(p_xh, p_wq, nullptr);

    // 2) tensor-core flash attention (128 q-rows / block) -> ga_h
    cudaFuncSetAttribute(attn_mma,
                         cudaFuncAttributeMaxDynamicSharedMemorySize, ATTN_SMEM_SZ);
    attn_mma<<<dim3(Tn / 128, Bn * Hn), 256, ATTN_SMEM_SZ>>>(pos);

    // 3) output projection -> d_out
    cudaFuncSetAttribute(tc_gemm<1, 1024>,
                         cudaFuncAttributeMaxDynamicSharedMemorySize, GEMM_SMEM);
    tc_gemm<1, 1024><<<dim3(8, 64), 256, GEMM_SMEM>>>(p_gah, p_wo, out);
}

// round 16
// speedup vs baseline: 1.0280x; 1.0121x over previous
#include <cuda_runtime.h>
#include <cuda_fp16.h>
#include <math.h>
#include <stdint.h>

// Problem constants
#define Bn 4
#define Tn 2048
#define Dn 1024
#define Hn 16
#define HDn 64
#define QKV_STRIDE (Bn * Hn * Tn * HDn)   // 8388608 elems per q/k/v

// ---------------------------------------------------------------------------
// Device scratch (no cudaMalloc allowed).  All u16 = fp16 bits.
// ---------------------------------------------------------------------------
__device__ unsigned short qkvh[3ull * QKV_STRIDE];      // [3][B][H][T][HD] fp16
__device__ unsigned short xa_h[(size_t)Bn * Tn * Dn];   // x fp16 [8192][1024]
__device__ unsigned short wq_h[(size_t)3 * Dn * Dn];    // Wqkv fp16 (native K-major)
__device__ unsigned short wo_h[(size_t)Dn * Dn];        // Wout fp16
__device__ unsigned short ga_h[(size_t)Bn * Tn * Dn];   // attention out fp16

// ---------------------------------------------------------------------------
// PTX helpers (non-arch-suffixed; valid on plain sm_103 target)
// ---------------------------------------------------------------------------
__device__ __forceinline__ uint32_t s2u(const void* p) {
    uint32_t a;
    asm("{ .reg .u64 t; cvta.to.shared.u64 t, %1; cvt.u32.u64 %0, t; }"
        : "=r"(a) : "l"(p));
    return a;
}
__device__ __forceinline__ void cpa16(uint32_t d, const void* s) {
    asm volatile("cp.async.cg.shared.global [%0], [%1], 16;"
                 :: "r"(d), "l"(s) : "memory");
}
__device__ __forceinline__ void cpa_commit() {
    asm volatile("cp.async.commit_group;" ::: "memory");
}
template<int N>
__device__ __forceinline__ void cpa_wait() {
    asm volatile("cp.async.wait_group %0;" :: "n"(N) : "memory");
}
__device__ __forceinline__ void ldsm4(uint32_t* r, uint32_t a) {
    asm volatile("ldmatrix.sync.aligned.m8n8.x4.shared.b16 {%0,%1,%2,%3}, [%4];"
        : "=r"(r[0]), "=r"(r[1]), "=r"(r[2]), "=r"(r[3]) : "r"(a));
}
__device__ __forceinline__ void ldsm4t(uint32_t* r, uint32_t a) {
    asm volatile("ldmatrix.sync.aligned.m8n8.x4.trans.shared.b16 {%0,%1,%2,%3}, [%4];"
        : "=r"(r[0]), "=r"(r[1]), "=r"(r[2]), "=r"(r[3]) : "r"(a));
}
__device__ __forceinline__ void mma16816(float* d, const uint32_t* a, const uint32_t* b) {
    asm volatile(
        "mma.sync.aligned.m16n8k16.row.col.f32.f16.f16.f32 "
        "{%0,%1,%2,%3}, {%4,%5,%6,%7}, {%8,%9}, {%0,%1,%2,%3};"
        : "+f"(d[0]), "+f"(d[1]), "+f"(d[2]), "+f"(d[3])
        : "r"(a[0]), "r"(a[1]), "r"(a[2]), "r"(a[3]), "r"(b[0]), "r"(b[1]));
}
__device__ __forceinline__ float ex2(float x) {
    float r;
    asm("ex2.approx.ftz.f32 %0, %1;" : "=f"(r) : "f"(x));
    return r;
}

// Swizzles
#define SWB(o) ((o) ^ ((((o) >> 8) & 7) << 4))   // 256B rows (GEMM B buf)
#define SW128(o) ((o) ^ ((((o) >> 7) & 7) << 4)) // 128B rows (GEMM A buf + attention)

// fp32 -> single fp16, fused over the three source arrays
__global__ __launch_bounds__(256)
void conv_fused_kernel(const float* __restrict__ x, unsigned short* __restrict__ xo,
                       const float* __restrict__ wq, unsigned short* __restrict__ wqo,
                       const float* __restrict__ wo, unsigned short* __restrict__ woo,
                       int nbx, int nbwq, int nbwo)
{
    const float* src;
    unsigned short* dst;
    int blk = blockIdx.x;
    if (blk < nbx) { src = x; dst = xo; }
    else if (blk < nbx + nbwq) { src = wq; dst = wqo; blk -= nbx; }
    else { src = wo; dst = woo; blk -= nbx + nbwq; }
    int i = blk * 256 + threadIdx.x;
    float4 v = ((const float4*)src)[i];
    __half a = __float2half_rn(v.x), b = __float2half_rn(v.y);
    __half c = __float2half_rn(v.z), d = __float2half_rn(v.w);
    ushort4 h;
    h.x = reinterpret_cast<unsigned short&>(a);
    h.y = reinterpret_cast<unsigned short&>(b);
    h.z = reinterpret_cast<unsigned short&>(c);
    h.w = reinterpret_cast<unsigned short&>(d);
    ((ushort4*)dst)[i] = h;
}

// ---------------------------------------------------------------------------
// Single-term fp16 GEMM via mma.sync: D[8192][NN] = Ah[8192][1024] @ Bh[1024][NN]
// 128x128 CTA tile, BK=64, 3-stage cp.async pipeline (32KB/stage), 8 warps
// (4m x 2n), warp tile 32x64, 64 MMAs per k-block, one sync per k-block,
// prefetch issued AFTER the first ks chunk (off the MMA critical path).
// 2 CTAs/SM enforced.  MODE 0: fp16 scatter into qkvh.  MODE 1: fp32 write.
// ---------------------------------------------------------------------------
#define BK 64
#define NKB2 16                        // 1024 / 64
#define STAGES 3
#define ABUF 16384                     // 128 rows x 64 fp16 (128B rows)
#define BBUF 16384                     // 64 rows x 128 fp16 (256B rows)
#define STG_BYTES (ABUF + BBUF)        // 32768

template<int MODE, int NN>
__global__ __launch_bounds__(256, 2)
void tc_gemm(const unsigned short* __restrict__ Ah,
             const unsigned short* __restrict__ Bh, float* __restrict__ Cout)
{
    extern __shared__ __align__(1024) unsigned char gsm[];
    const uint32_t sbase = s2u(gsm);
    const int tid = threadIdx.x;
    const int lane = tid & 31, wid = tid >> 5;
    const int wm = wid & 3, wn = wid >> 2;
    const int bm = blockIdx.y * 128, bn = blockIdx.x * 128;

    const unsigned short* Abase = Ah + (size_t)bm * 1024;
    const unsigned short* Bbase = Bh + bn;

    auto load_stage = [&](int st, int kb) {
        uint32_t sb = sbase + st * STG_BYTES;
#pragma unroll
        for (int i = 0; i < 4; i++) {
            int id = i * 256 + tid;
            int r = id >> 3, c = id & 7;
            cpa16(sb + SW128(r * 128 + c * 16),
                  Abase + (size_t)r * 1024 + kb * BK + c * 8);
        }
#pragma unroll
        for (int i = 0; i < 4; i++) {
            int id = i * 256 + tid;
            int rk = id >> 4, cc = id & 15;
            cpa16(sb + ABUF + SWB(rk * 256 + cc * 16),
                  Bbase + (size_t)(kb * BK + rk) * NN + cc * 8);
        }
    };

    float acc[2][8][4];
#pragma unroll
    for (int mt = 0; mt < 2; mt++)
#pragma unroll
        for (int nt = 0; nt < 8; nt++)
#pragma unroll
            for (int q = 0; q < 4; q++) acc[mt][nt][q] = 0.f;

    load_stage(0, 0); cpa_commit();
    load_stage(1, 1); cpa_commit();

    const int a_lr = lane & 15;
    const int a_hk = (lane >> 4) << 4;

    // one ks chunk: fragment loads + 16 MMAs
    auto do_ks = [&](uint32_t sb, int ks) {
        uint32_t afr[2][4];
#pragma unroll
        for (int mt = 0; mt < 2; mt++) {
            int r = wm * 32 + mt * 16 + a_lr;
            ldsm4(afr[mt], sb + SW128(r * 128 + ks * 32 + a_hk));
        }
        uint32_t bfr[8][2];
#pragma unroll
        for (int nt2 = 0; nt2 < 4; nt2++) {
            int kk = ks * 16 + a_lr;
            int nb = wn * 128 + nt2 * 32 + a_hk;
            uint32_t t[4];
            ldsm4t(t, sb + ABUF + SWB(kk * 256 + nb));
            bfr[nt2 * 2][0] = t[0]; bfr[nt2 * 2][1] = t[1];
            bfr[nt2 * 2 + 1][0] = t[2]; bfr[nt2 * 2 + 1][1] = t[3];
        }
#pragma unroll
        for (int mt = 0; mt < 2; mt++)
#pragma unroll
            for (int nt = 0; nt < 8; nt++)
                mma16816(acc[mt][nt], afr[mt], bfr[nt]);
    };

    for (int kb = 0; kb < NKB2; kb++) {
        const int cur = kb % STAGES;
        cpa_wait<1>();
        __syncthreads();

        uint32_t sb = sbase + cur * STG_BYTES;
        do_ks(sb, 0);                       // restart tensor pipe first
        if (kb + 2 < NKB2) load_stage((kb + 2) % STAGES, kb + 2);
        cpa_commit();                       // prefetch off the critical path
#pragma unroll
        for (int ks = 1; ks < 4; ks++) do_ks(sb, ks);
    }

    const int gid = lane >> 2, tg = lane & 3;
#pragma unroll
    for (int mt = 0; mt < 2; mt++)
#pragma unroll
        for (int nt = 0; nt < 8; nt++) {
            int row0 = bm + wm * 32 + mt * 16 + gid;
            int col = bn + wn * 64 + nt * 8 + tg * 2;
#pragma unroll
            for (int half = 0; half < 2; half++) {
                int row = row0 + half * 8;
                float v0 = acc[mt][nt][half * 2], v1 = acc[mt][nt][half * 2 + 1];
                if (MODE == 0) {
                    int s = col >> 10, h = (col >> 6) & 15, d = col & 63;
                    int b = row >> 11, t = row & 2047;
                    size_t idx = (size_t)s * QKV_STRIDE +
                                 (((size_t)(b * Hn + h) * Tn + t) << 6) + d;
                    __half h0 = __float2half_rn(v0), h1 = __float2half_rn(v1);
                    *(uint32_t*)&qkvh[idx] =
                        (uint32_t)reinterpret_cast<unsigned short&>(h0) |
                        ((uint32_t)reinterpret_cast<unsigned short&>(h1) << 16);
                } else {
                    *(float2*)&Cout[(size_t)row * NN + col] = make_float2(v0, v1);
                }
            }
        }
}

// ---------------------------------------------------------------------------
// Tensor-core flash attention, single-term fp16 (fp32 accum).
// 256 threads = 8 warps; 128 q rows per block.  2 CTAs/SM.
// Raw-logit softmax (ex2.approx, scale folded), mask-free fast path,
// descending tile order, prefetch issued after the first QK ks chunk.
// ---------------------------------------------------------------------------
#define AQ_OFF 0                     // Q 16KB (128 rows x 128B)
#define AKV_OFF 16384                // 2 stages x (K 8KB + V 8KB)
#define APOS_OFF (16384 + 32768)     // 49152
#define ATTN_SMEM_SZ (16384 + 32768 + 512)

__global__ __launch_bounds__(256, 2)
void attn_mma(const int* __restrict__ pos)
{
    extern __shared__ __align__(1024) unsigned char am[];
    const uint32_t sb = s2u(am);
    const int tid = threadIdx.x, lane = tid & 31, wm = tid >> 5;   // wm 0..7
    const int b = blockIdx.y >> 4, h = blockIdx.y & 15;
    const int i0 = (15 - blockIdx.x) * 128;    // heavy tiles scheduled first

    const size_t bh_off = ((size_t)(b * Hn + h) * Tn) << 6;
    const unsigned short* Qhg = qkvh + bh_off + ((size_t)i0 << 6);
    const unsigned short* Khg = qkvh + (size_t)QKV_STRIDE + bh_off;
    const unsigned short* Vhg = qkvh + 2ull * QKV_STRIDE + bh_off;
    const int* posb = pos + b * Tn;

    // Q tile (128 rows) -> smem: 1024 16B-chunks
#pragma unroll
    for (int i = 0; i < 4; i++) {
        int id = tid + i * 256;
        int r = id >> 3, c = id & 7;
        cpa16(sb + AQ_OFF + SW128(r * 128 + c * 16), Qhg + (size_t)r * 64 + c * 8);
    }
    cpa_commit();

    auto load_kv = [&](int st, int j0) {
        uint32_t base = sb + AKV_OFF + st * 16384;
        const unsigned short* srcs[2] = {
            Khg + ((size_t)j0 << 6), Vhg + ((size_t)j0 << 6) };
#pragma unroll
        for (int buf = 0; buf < 2; buf++)
#pragma unroll
            for (int i = 0; i < 2; i++) {
                int id = tid + i * 256;      // 0..511
                int r = id >> 3, c = id & 7;
                cpa16(base + buf * 8192 + SW128(r * 128 + c * 16),
                      srcs[buf] + (size_t)r * 64 + c * 8);
            }
        if (tid < 16)
            cpa16(sb + APOS_OFF + st * 256 + tid * 16, posb + j0 + tid * 4);
    };

    load_kv(0, 0);
    cpa_commit();

    cpa_wait<1>();
    __syncthreads();
    const int a_lr = lane & 15, a_hk = (lane >> 4) << 4;
    uint32_t qfh[4][4];
#pragma unroll
    for (int ks = 0; ks < 4; ks++) {
        int r = wm * 16 + a_lr;
        ldsm4(qfh[ks], sb + AQ_OFF + SW128(r * 128 + ks * 32 + a_hk));
    }

    const int pq0 = posb[i0 + wm * 16 + (lane >> 2)];
    const int pq1 = posb[i0 + wm * 16 + (lane >> 2) + 8];
    const int pqmin = posb[i0];
    const int pqmax = posb[i0 + 127];
    const int jcol = 2 * (lane & 3);

    float m0 = -3e38f, m1 = -3e38f, l0 = 0.f, l1 = 0.f;
    float oacc[8][4];
#pragma unroll
    for (int nt = 0; nt < 8; nt++)
#pragma unroll
        for (int q = 0; q < 4; q++) oacc[nt][q] = 0.f;

    const float CS = 0.18033688011112042f;   // 0.125 * log2(e)

    int jb = 0, st = 0;
    for (;;) {
        int next = jb + 64;
        bool hn = (next < Tn) && (posb[next] <= pqmax);

        cpa_wait<0>();          // current stage fully resident
        __syncthreads();        // seals last iter's reads of stage st^1

        const uint32_t kb_ = sb + AKV_OFF + st * 16384;
        const int* pkp = (const int*)(am + APOS_OFF + st * 256);

        float sacc[8][4];
#pragma unroll
        for (int nt = 0; nt < 8; nt++)
#pragma unroll
            for (int q = 0; q < 4; q++) sacc[nt][q] = 0.f;

        // QK ks chunk helper
        auto qk_ks = [&](int ks) {
            uint32_t kf[4][4];
            const int g = lane >> 3;
            const int krow = (g >> 1) * 8 + (lane & 7);
            const int kchk = ks * 32 + (g & 1) * 16;
#pragma unroll
            for (int call = 0; call < 4; call++) {
                uint32_t off = SW128((call * 16 + krow) * 128 + kchk);
                ldsm4(kf[call], kb_ + off);
            }
#pragma unroll
            for (int nt = 0; nt < 8; nt++) {
                const int c = nt >> 1, hf = (nt & 1) * 2;
                mma16816(sacc[nt], qfh[ks], &kf[c][hf]);
            }
        };

        qk_ks(0);                          // restart tensor pipe first
        if (hn) load_kv(st ^ 1, next);     // prefetch off the critical path
        cpa_commit();
        qk_ks(1); qk_ks(2); qk_ks(3);

        // ---- online softmax on RAW logits; scale folded into exp ----
        const bool need_mask = (pkp[63] > pqmin);
        float mx0 = m0, mx1 = m1;
        if (need_mask) {
#pragma unroll
            for (int nt = 0; nt < 8; nt++) {
                int pk0 = pkp[nt * 8 + jcol], pk1 = pkp[nt * 8 + jcol + 1];
                float v0 = (pq0 < pk0) ? -3e38f : sacc[nt][0];
                float v1 = (pq0 < pk1) ? -3e38f : sacc[nt][1];
                float v2 = (pq1 < pk0) ? -3e38f : sacc[nt][2];
                float v3 = (pq1 < pk1) ? -3e38f : sacc[nt][3];
                sacc[nt][0] = v0; sacc[nt][1] = v1;
                sacc[nt][2] = v2; sacc[nt][3] = v3;
                mx0 = fmaxf(mx0, fmaxf(v0, v1));
                mx1 = fmaxf(mx1, fmaxf(v2, v3));
            }
        } else {
#pragma unroll
            for (int nt = 0; nt < 8; nt++) {
                mx0 = fmaxf(mx0, fmaxf(sacc[nt][0], sacc[nt][1]));
                mx1 = fmaxf(mx1, fmaxf(sacc[nt][2], sacc[nt][3]));
            }
        }
        mx0 = fmaxf(mx0, __shfl_xor_sync(0xffffffffu, mx0, 1));
        mx0 = fmaxf(mx0, __shfl_xor_sync(0xffffffffu, mx0, 2));
        mx1 = fmaxf(mx1, __shfl_xor_sync(0xffffffffu, mx1, 1));
        mx1 = fmaxf(mx1, __shfl_xor_sync(0xffffffffu, mx1, 2));
        float al0 = ex2((m0 - mx0) * CS), al1 = ex2((m1 - mx1) * CS);
        m0 = mx0; m1 = mx1;
        const float c0 = -mx0 * CS, c1 = -mx1 * CS;

        float s0 = 0.f, s1 = 0.f;
#pragma unroll
        for (int nt = 0; nt < 8; nt++) {
            float p0 = ex2(fmaf(sacc[nt][0], CS, c0));
            float p1 = ex2(fmaf(sacc[nt][1], CS, c0));
            float p2 = ex2(fmaf(sacc[nt][2], CS, c1));
            float p3 = ex2(fmaf(sacc[nt][3], CS, c1));
            sacc[nt][0] = p0; sacc[nt][1] = p1;
            sacc[nt][2] = p2; sacc[nt][3] = p3;
            s0 += p0 + p1; s1 += p2 + p3;
        }
        s0 += __shfl_xor_sync(0xffffffffu, s0, 1);
        s0 += __shfl_xor_sync(0xffffffffu, s0, 2);
        s1 += __shfl_xor_sync(0xffffffffu, s1, 1);
        s1 += __shfl_xor_sync(0xffffffffu, s1, 2);
        l0 = l0 * al0 + s0;
        l1 = l1 * al1 + s1;
#pragma unroll
        for (int nt = 0; nt < 8; nt++) {
            oacc[nt][0] *= al0; oacc[nt][1] *= al0;
            oacc[nt][2] *= al1; oacc[nt][3] *= al1;
        }

        const uint32_t vb = kb_ + 8192;
#pragma unroll
        for (int kt = 0; kt < 4; kt++) {
            uint32_t ph[4];
#pragma unroll
            for (int q = 0; q < 4; q++) {
                const float* src = (q < 2) ? sacc[2 * kt] : sacc[2 * kt + 1];
                float a = src[(q & 1) * 2], c = src[(q & 1) * 2 + 1];
                __half ha = __float2half_rn(a), hc = __float2half_rn(c);
                ph[q] = (uint32_t)reinterpret_cast<unsigned short&>(ha) |
                        ((uint32_t)reinterpret_cast<unsigned short&>(hc) << 16);
            }
            uint32_t vf[4][4];
#pragma unroll
            for (int call = 0; call < 4; call++) {
                uint32_t off = SW128((kt * 16 + a_lr) * 128 + call * 32 + a_hk);
                ldsm4t(vf[call], vb + off);
            }
#pragma unroll
            for (int nt = 0; nt < 8; nt++) {
                const int c = nt >> 1, hf = (nt & 1) * 2;
                mma16816(oacc[nt], ph, &vf[c][hf]);
            }
        }

        if (!hn) break;
        jb = next; st ^= 1;
    }

    // Epilogue: normalize, write single fp16 to ga_h
    float inv0 = 1.f / l0, inv1 = 1.f / l1;
    int t0r = i0 + wm * 16 + (lane >> 2);
#pragma unroll
    for (int nt = 0; nt < 8; nt++) {
        int col = h * 64 + nt * 8 + jcol;
#pragma unroll
        for (int half = 0; half < 2; half++) {
            int t = t0r + half * 8;
            float inv = half ? inv1 : inv0;
            float v0 = oacc[nt][half * 2] * inv;
            float v1 = oacc[nt][half * 2 + 1] * inv;
            __half h0 = __float2half_rn(v0), h1 = __float2half_rn(v1);
            size_t idx = ((size_t)b * Tn + t) * Dn + col;
            *(uint32_t*)&ga_h[idx] =
                (uint32_t)reinterpret_cast<unsigned short&>(h0) |
                ((uint32_t)reinterpret_cast<unsigned short&>(h1) << 16);
        }
    }
}

// ---------------------------------------------------------------------------
extern "C" void kernel_launch(void* const* d_in, const int* in_sizes, int n_in,
                              void* d_out, int out_size)
{
    const float* x   = (const float*)d_in[0];
    const int*   pos = (const int*)d_in[1];
    const float* Wq  = (const float*)d_in[2];
    const float* Wo  = (const float*)d_in[3];
    float* out = (float*)d_out;

    unsigned short *p_xh, *p_wq, *p_wo, *p_gah;
    cudaGetSymbolAddress((void**)&p_xh,  xa_h);
    cudaGetSymbolAddress((void**)&p_wq,  wq_h);
    cudaGetSymbolAddress((void**)&p_wo,  wo_h);
    cudaGetSymbolAddress((void**)&p_gah, ga_h);

    const int GEMM_SMEM = STAGES * STG_BYTES;   // 98304

    // 0) fused fp16 conversions (x, Wqkv, Wout in one launch)
    int nbx  = (Bn * Tn * Dn) / 4 / 256;     // 2048 blocks
    int nbwq = (3 * Dn * Dn) / 4 / 256;      // 3072 blocks
    int nbwo = (Dn * Dn) / 4 / 256;          // 1024 blocks
    conv_fused_kernel<<<nbx + nbwq + nbwo, 256>>>(x, p_xh, Wq, p_wq, Wo, p_wo,
                                                  nbx, nbwq, nbwo);

    // 1) QKV projection -> qkvh
    cudaFuncSetAttribute(tc_gemm<0, 3072>,
                         cudaFuncAttributeMaxDynamicSharedMemorySize, GEMM_SMEM);
    tc_gemm<0, 3072><<<dim3(24, 64), 256, GEMM_SMEM>>>(p_xh, p_wq, nullptr);

    // 2) tensor-core flash attention (128 q-rows / block) -> ga_h
    cudaFuncSetAttribute(attn_mma,
                         cudaFuncAttributeMaxDynamicSharedMemorySize, ATTN_SMEM_SZ);
    attn_mma<<<dim3(Tn / 128, Bn * Hn), 256, ATTN_SMEM_SZ>>>(pos);

    // 3) output projection -> d_out
    cudaFuncSetAttribute(tc_gemm<1, 1024>,
                         cudaFuncAttributeMaxDynamicSharedMemorySize, GEMM_SMEM);
    tc_gemm<1, 1024><<<dim3(8, 64), 256, GEMM_SMEM>>>(p_gah, p_wo, out);
}

// round 17
// speedup vs baseline: 1.0459x; 1.0174x over previous
#include <cuda_runtime.h>
#include <cuda_fp16.h>
#include <math.h>
#include <stdint.h>

// Problem constants
#define Bn 4
#define Tn 2048
#define Dn 1024
#define Hn 16
#define HDn 64
#define QKV_STRIDE (Bn * Hn * Tn * HDn)   // 8388608 elems per q/k/v

// ---------------------------------------------------------------------------
// Device scratch (no cudaMalloc allowed).  All u16 = fp16 bits.
// ---------------------------------------------------------------------------
__device__ unsigned short qkvh[3ull * QKV_STRIDE];      // [3][B][H][T][HD] fp16
__device__ unsigned short xa_h[(size_t)Bn * Tn * Dn];   // x fp16 [8192][1024]
__device__ unsigned short wq_h[(size_t)3 * Dn * Dn];    // Wqkv fp16 (native K-major)
__device__ unsigned short wo_h[(size_t)Dn * Dn];        // Wout fp16
__device__ unsigned short ga_h[(size_t)Bn * Tn * Dn];   // attention out fp16

// ---------------------------------------------------------------------------
// PTX helpers (non-arch-suffixed; valid on plain sm_103 target)
// ---------------------------------------------------------------------------
__device__ __forceinline__ uint32_t s2u(const void* p) {
    uint32_t a;
    asm("{ .reg .u64 t; cvta.to.shared.u64 t, %1; cvt.u32.u64 %0, t; }"
        : "=r"(a) : "l"(p));
    return a;
}
__device__ __forceinline__ void cpa16(uint32_t d, const void* s) {
    asm volatile("cp.async.cg.shared.global [%0], [%1], 16;"
                 :: "r"(d), "l"(s) : "memory");
}
__device__ __forceinline__ void cpa_commit() {
    asm volatile("cp.async.commit_group;" ::: "memory");
}
template<int N>
__device__ __forceinline__ void cpa_wait() {
    asm volatile("cp.async.wait_group %0;" :: "n"(N) : "memory");
}
__device__ __forceinline__ void ldsm4(uint32_t* r, uint32_t a) {
    asm volatile("ldmatrix.sync.aligned.m8n8.x4.shared.b16 {%0,%1,%2,%3}, [%4];"
        : "=r"(r[0]), "=r"(r[1]), "=r"(r[2]), "=r"(r[3]) : "r"(a));
}
__device__ __forceinline__ void ldsm4t(uint32_t* r, uint32_t a) {
    asm volatile("ldmatrix.sync.aligned.m8n8.x4.trans.shared.b16 {%0,%1,%2,%3}, [%4];"
        : "=r"(r[0]), "=r"(r[1]), "=r"(r[2]), "=r"(r[3]) : "r"(a));
}
__device__ __forceinline__ void mma16816(float* d, const uint32_t* a, const uint32_t* b) {
    asm volatile(
        "mma.sync.aligned.m16n8k16.row.col.f32.f16.f16.f32 "
        "{%0,%1,%2,%3}, {%4,%5,%6,%7}, {%8,%9}, {%0,%1,%2,%3};"
        : "+f"(d[0]), "+f"(d[1]), "+f"(d[2]), "+f"(d[3])
        : "r"(a[0]), "r"(a[1]), "r"(a[2]), "r"(a[3]), "r"(b[0]), "r"(b[1]));
}
__device__ __forceinline__ float ex2(float x) {
    float r;
    asm("ex2.approx.ftz.f32 %0, %1;" : "=f"(r) : "f"(x));
    return r;
}

// Swizzles
#define SWB(o) ((o) ^ ((((o) >> 8) & 7) << 4))   // 256B rows (GEMM B buf)
#define SW128(o) ((o) ^ ((((o) >> 7) & 7) << 4)) // 128B rows (GEMM A buf + attention)

// fp32 -> single fp16, fused over the three source arrays
__global__ __launch_bounds__(256)
void conv_fused_kernel(const float* __restrict__ x, unsigned short* __restrict__ xo,
                       const float* __restrict__ wq, unsigned short* __restrict__ wqo,
                       const float* __restrict__ wo, unsigned short* __restrict__ woo,
                       int nbx, int nbwq, int nbwo)
{
    const float* src;
    unsigned short* dst;
    int blk = blockIdx.x;
    if (blk < nbx) { src = x; dst = xo; }
    else if (blk < nbx + nbwq) { src = wq; dst = wqo; blk -= nbx; }
    else { src = wo; dst = woo; blk -= nbx + nbwq; }
    int i = blk * 256 + threadIdx.x;
    float4 v = ((const float4*)src)[i];
    __half a = __float2half_rn(v.x), b = __float2half_rn(v.y);
    __half c = __float2half_rn(v.z), d = __float2half_rn(v.w);
    ushort4 h;
    h.x = reinterpret_cast<unsigned short&>(a);
    h.y = reinterpret_cast<unsigned short&>(b);
    h.z = reinterpret_cast<unsigned short&>(c);
    h.w = reinterpret_cast<unsigned short&>(d);
    ((ushort4*)dst)[i] = h;
}

// ---------------------------------------------------------------------------
// Single-term fp16 GEMM via mma.sync (R16 config, unchanged).
// ---------------------------------------------------------------------------
#define BK 64
#define NKB2 16                        // 1024 / 64
#define STAGES 3
#define ABUF 16384                     // 128 rows x 64 fp16 (128B rows)
#define BBUF 16384                     // 64 rows x 128 fp16 (256B rows)
#define STG_BYTES (ABUF + BBUF)        // 32768

template<int MODE, int NN>
__global__ __launch_bounds__(256, 2)
void tc_gemm(const unsigned short* __restrict__ Ah,
             const unsigned short* __restrict__ Bh, float* __restrict__ Cout)
{
    extern __shared__ __align__(1024) unsigned char gsm[];
    const uint32_t sbase = s2u(gsm);
    const int tid = threadIdx.x;
    const int lane = tid & 31, wid = tid >> 5;
    const int wm = wid & 3, wn = wid >> 2;
    const int bm = blockIdx.y * 128, bn = blockIdx.x * 128;

    const unsigned short* Abase = Ah + (size_t)bm * 1024;
    const unsigned short* Bbase = Bh + bn;

    auto load_stage = [&](int st, int kb) {
        uint32_t sb = sbase + st * STG_BYTES;
#pragma unroll
        for (int i = 0; i < 4; i++) {
            int id = i * 256 + tid;
            int r = id >> 3, c = id & 7;
            cpa16(sb + SW128(r * 128 + c * 16),
                  Abase + (size_t)r * 1024 + kb * BK + c * 8);
        }
#pragma unroll
        for (int i = 0; i < 4; i++) {
            int id = i * 256 + tid;
            int rk = id >> 4, cc = id & 15;
            cpa16(sb + ABUF + SWB(rk * 256 + cc * 16),
                  Bbase + (size_t)(kb * BK + rk) * NN + cc * 8);
        }
    };

    float acc[2][8][4];
#pragma unroll
    for (int mt = 0; mt < 2; mt++)
#pragma unroll
        for (int nt = 0; nt < 8; nt++)
#pragma unroll
            for (int q = 0; q < 4; q++) acc[mt][nt][q] = 0.f;

    load_stage(0, 0); cpa_commit();
    load_stage(1, 1); cpa_commit();

    const int a_lr = lane & 15;
    const int a_hk = (lane >> 4) << 4;

    auto do_ks = [&](uint32_t sb, int ks) {
        uint32_t afr[2][4];
#pragma unroll
        for (int mt = 0; mt < 2; mt++) {
            int r = wm * 32 + mt * 16 + a_lr;
            ldsm4(afr[mt], sb + SW128(r * 128 + ks * 32 + a_hk));
        }
        uint32_t bfr[8][2];
#pragma unroll
        for (int nt2 = 0; nt2 < 4; nt2++) {
            int kk = ks * 16 + a_lr;
            int nb = wn * 128 + nt2 * 32 + a_hk;
            uint32_t t[4];
            ldsm4t(t, sb + ABUF + SWB(kk * 256 + nb));
            bfr[nt2 * 2][0] = t[0]; bfr[nt2 * 2][1] = t[1];
            bfr[nt2 * 2 + 1][0] = t[2]; bfr[nt2 * 2 + 1][1] = t[3];
        }
#pragma unroll
        for (int mt = 0; mt < 2; mt++)
#pragma unroll
            for (int nt = 0; nt < 8; nt++)
                mma16816(acc[mt][nt], afr[mt], bfr[nt]);
    };

    for (int kb = 0; kb < NKB2; kb++) {
        const int cur = kb % STAGES;
        cpa_wait<1>();
        __syncthreads();

        uint32_t sb = sbase + cur * STG_BYTES;
        do_ks(sb, 0);
        if (kb + 2 < NKB2) load_stage((kb + 2) % STAGES, kb + 2);
        cpa_commit();
#pragma unroll
        for (int ks = 1; ks < 4; ks++) do_ks(sb, ks);
    }

    const int gid = lane >> 2, tg = lane & 3;
#pragma unroll
    for (int mt = 0; mt < 2; mt++)
#pragma unroll
        for (int nt = 0; nt < 8; nt++) {
            int row0 = bm + wm * 32 + mt * 16 + gid;
            int col = bn + wn * 64 + nt * 8 + tg * 2;
#pragma unroll
            for (int half = 0; half < 2; half++) {
                int row = row0 + half * 8;
                float v0 = acc[mt][nt][half * 2], v1 = acc[mt][nt][half * 2 + 1];
                if (MODE == 0) {
                    int s = col >> 10, h = (col >> 6) & 15, d = col & 63;
                    int b = row >> 11, t = row & 2047;
                    size_t idx = (size_t)s * QKV_STRIDE +
                                 (((size_t)(b * Hn + h) * Tn + t) << 6) + d;
                    __half h0 = __float2half_rn(v0), h1 = __float2half_rn(v1);
                    *(uint32_t*)&qkvh[idx] =
                        (uint32_t)reinterpret_cast<unsigned short&>(h0) |
                        ((uint32_t)reinterpret_cast<unsigned short&>(h1) << 16);
                } else {
                    *(float2*)&Cout[(size_t)row * NN + col] = make_float2(v0, v1);
                }
            }
        }
}

// ---------------------------------------------------------------------------
// Tensor-core flash attention, single-term fp16 (fp32 accum).
// 256 threads = 8 warps; 128 q rows per block.  2 CTAs/SM.
// 3-stage KV ring (prefetch 2 iters ahead, cpa_wait<1>), raw-logit softmax
// (ex2.approx), warp-uniform rescale skip, mask-free fast path, descending
// tile order.  Sorted positions guarantee >= 2 kv iterations per tile.
// ---------------------------------------------------------------------------
#define AQ_OFF 0                       // Q 16KB (128 rows x 128B)
#define AKV_OFF 16384                  // 3 stages x (K 8KB + V 8KB)
#define APOS_OFF (16384 + 49152)       // 65536, 3 x 256B
#define ATTN_SMEM_SZ (16384 + 49152 + 768)

__global__ __launch_bounds__(256, 2)
void attn_mma(const int* __restrict__ pos)
{
    extern __shared__ __align__(1024) unsigned char am[];
    const uint32_t sb = s2u(am);
    const int tid = threadIdx.x, lane = tid & 31, wm = tid >> 5;   // wm 0..7
    const int b = blockIdx.y >> 4, h = blockIdx.y & 15;
    const int i0 = (15 - blockIdx.x) * 128;    // heavy tiles scheduled first

    const size_t bh_off = ((size_t)(b * Hn + h) * Tn) << 6;
    const unsigned short* Qhg = qkvh + bh_off + ((size_t)i0 << 6);
    const unsigned short* Khg = qkvh + (size_t)QKV_STRIDE + bh_off;
    const unsigned short* Vhg = qkvh + 2ull * QKV_STRIDE + bh_off;
    const int* posb = pos + b * Tn;

    // Q tile (128 rows) -> smem: 1024 16B-chunks (group 0)
#pragma unroll
    for (int i = 0; i < 4; i++) {
        int id = tid + i * 256;
        int r = id >> 3, c = id & 7;
        cpa16(sb + AQ_OFF + SW128(r * 128 + c * 16), Qhg + (size_t)r * 64 + c * 8);
    }
    cpa_commit();

    auto load_kv = [&](int st, int j0) {
        uint32_t base = sb + AKV_OFF + st * 16384;
        const unsigned short* srcs[2] = {
            Khg + ((size_t)j0 << 6), Vhg + ((size_t)j0 << 6) };
#pragma unroll
        for (int buf = 0; buf < 2; buf++)
#pragma unroll
            for (int i = 0; i < 2; i++) {
                int id = tid + i * 256;      // 0..511
                int r = id >> 3, c = id & 7;
                cpa16(base + buf * 8192 + SW128(r * 128 + c * 16),
                      srcs[buf] + (size_t)r * 64 + c * 8);
            }
        if (tid < 16)
            cpa16(sb + APOS_OFF + st * 256 + tid * 16, posb + j0 + tid * 4);
    };

    // Prologue: stages 0 and 1 (every tile runs >= 2 iterations: positions
    // are sorted so posb[64] <= posb[i0+127] always).
    load_kv(0, 0);  cpa_commit();      // group 1
    load_kv(1, 64); cpa_commit();      // group 2

    cpa_wait<1>();                     // Q + stage0 resident (stage1 may fly)
    __syncthreads();
    const int a_lr = lane & 15, a_hk = (lane >> 4) << 4;
    uint32_t qfh[4][4];
#pragma unroll
    for (int ks = 0; ks < 4; ks++) {
        int r = wm * 16 + a_lr;
        ldsm4(qfh[ks], sb + AQ_OFF + SW128(r * 128 + ks * 32 + a_hk));
    }

    const int pq0 = posb[i0 + wm * 16 + (lane >> 2)];
    const int pq1 = posb[i0 + wm * 16 + (lane >> 2) + 8];
    const int pqmin = posb[i0];
    const int pqmax = posb[i0 + 127];
    const int jcol = 2 * (lane & 3);

    float m0 = -3e38f, m1 = -3e38f, l0 = 0.f, l1 = 0.f;
    float oacc[8][4];
#pragma unroll
    for (int nt = 0; nt < 8; nt++)
#pragma unroll
        for (int q = 0; q < 4; q++) oacc[nt][q] = 0.f;

    const float CS = 0.18033688011112042f;   // 0.125 * log2(e)

    int jb = 0, st = 0;
    for (;;) {
        int next = jb + 64;
        bool hn = (next < Tn) && (posb[next] <= pqmax);
        int n2 = jb + 128;
        bool hn2 = (n2 < Tn) && (posb[n2] <= pqmax);

        const uint32_t kb_ = sb + AKV_OFF + st * 16384;
        const int* pkp = (const int*)(am + APOS_OFF + st * 256);

        float sacc[8][4];
#pragma unroll
        for (int nt = 0; nt < 8; nt++)
#pragma unroll
            for (int q = 0; q < 4; q++) sacc[nt][q] = 0.f;

        auto qk_ks = [&](int ks) {
            uint32_t kf[4][4];
            const int g = lane >> 3;
            const int krow = (g >> 1) * 8 + (lane & 7);
            const int kchk = ks * 32 + (g & 1) * 16;
#pragma unroll
            for (int call = 0; call < 4; call++) {
                uint32_t off = SW128((call * 16 + krow) * 128 + kchk);
                ldsm4(kf[call], kb_ + off);
            }
#pragma unroll
            for (int nt = 0; nt < 8; nt++) {
                const int c = nt >> 1, hf = (nt & 1) * 2;
                mma16816(sacc[nt], qfh[ks], &kf[c][hf]);
            }
        };

        qk_ks(0);                          // restart tensor pipe first
        if (hn2) {
            int st2 = st + 2; if (st2 >= 3) st2 -= 3;
            load_kv(st2, n2);              // prefetch 2 iterations ahead
        }
        cpa_commit();                      // unconditional: uniform group count
        qk_ks(1); qk_ks(2); qk_ks(3);

        // ---- online softmax on RAW logits; scale folded into exp ----
        const bool need_mask = (pkp[63] > pqmin);
        float mx0 = m0, mx1 = m1;
        if (need_mask) {
#pragma unroll
            for (int nt = 0; nt < 8; nt++) {
                int pk0 = pkp[nt * 8 + jcol], pk1 = pkp[nt * 8 + jcol + 1];
                float v0 = (pq0 < pk0) ? -3e38f : sacc[nt][0];
                float v1 = (pq0 < pk1) ? -3e38f : sacc[nt][1];
                float v2 = (pq1 < pk0) ? -3e38f : sacc[nt][2];
                float v3 = (pq1 < pk1) ? -3e38f : sacc[nt][3];
                sacc[nt][0] = v0; sacc[nt][1] = v1;
                sacc[nt][2] = v2; sacc[nt][3] = v3;
                mx0 = fmaxf(mx0, fmaxf(v0, v1));
                mx1 = fmaxf(mx1, fmaxf(v2, v3));
            }
        } else {
#pragma unroll
            for (int nt = 0; nt < 8; nt++) {
                mx0 = fmaxf(mx0, fmaxf(sacc[nt][0], sacc[nt][1]));
                mx1 = fmaxf(mx1, fmaxf(sacc[nt][2], sacc[nt][3]));
            }
        }
        mx0 = fmaxf(mx0, __shfl_xor_sync(0xffffffffu, mx0, 1));
        mx0 = fmaxf(mx0, __shfl_xor_sync(0xffffffffu, mx0, 2));
        mx1 = fmaxf(mx1, __shfl_xor_sync(0xffffffffu, mx1, 1));
        mx1 = fmaxf(mx1, __shfl_xor_sync(0xffffffffu, mx1, 2));
        float al0 = ex2((m0 - mx0) * CS), al1 = ex2((m1 - mx1) * CS);
        m0 = mx0; m1 = mx1;
        const float c0 = -mx0 * CS, c1 = -mx1 * CS;

        float s0 = 0.f, s1 = 0.f;
#pragma unroll
        for (int nt = 0; nt < 8; nt++) {
            float p0 = ex2(fmaf(sacc[nt][0], CS, c0));
            float p1 = ex2(fmaf(sacc[nt][1], CS, c0));
            float p2 = ex2(fmaf(sacc[nt][2], CS, c1));
            float p3 = ex2(fmaf(sacc[nt][3], CS, c1));
            sacc[nt][0] = p0; sacc[nt][1] = p1;
            sacc[nt][2] = p2; sacc[nt][3] = p3;
            s0 += p0 + p1; s1 += p2 + p3;
        }
        s0 += __shfl_xor_sync(0xffffffffu, s0, 1);
        s0 += __shfl_xor_sync(0xffffffffu, s0, 2);
        s1 += __shfl_xor_sync(0xffffffffu, s1, 1);
        s1 += __shfl_xor_sync(0xffffffffu, s1, 2);
        l0 = l0 * al0 + s0;
        l1 = l1 * al1 + s1;

        // Warp-uniform rescale skip: al==1.0 exactly when max unchanged
        if (__any_sync(0xffffffffu, (al0 != 1.f) | (al1 != 1.f))) {
#pragma unroll
            for (int nt = 0; nt < 8; nt++) {
                oacc[nt][0] *= al0; oacc[nt][1] *= al0;
                oacc[nt][2] *= al1; oacc[nt][3] *= al1;
            }
        }

        const uint32_t vb = kb_ + 8192;
#pragma unroll
        for (int kt = 0; kt < 4; kt++) {
            uint32_t ph[4];
#pragma unroll
            for (int q = 0; q < 4; q++) {
                const float* src = (q < 2) ? sacc[2 * kt] : sacc[2 * kt + 1];
                float a = src[(q & 1) * 2], c = src[(q & 1) * 2 + 1];
                __half ha = __float2half_rn(a), hc = __float2half_rn(c);
                ph[q] = (uint32_t)reinterpret_cast<unsigned short&>(ha) |
                        ((uint32_t)reinterpret_cast<unsigned short&>(hc) << 16);
            }
            uint32_t vf[4][4];
#pragma unroll
            for (int call = 0; call < 4; call++) {
                uint32_t off = SW128((kt * 16 + a_lr) * 128 + call * 32 + a_hk);
                ldsm4t(vf[call], vb + off);
            }
#pragma unroll
            for (int nt = 0; nt < 8; nt++) {
                const int c = nt >> 1, hf = (nt & 1) * 2;
                mma16816(oacc[nt], ph, &vf[c][hf]);
            }
        }

        if (!hn) break;
        jb = next;
        st = st + 1; if (st >= 3) st -= 3;
        cpa_wait<1>();          // stage for this iter (issued 2 iters ago) ready
        __syncthreads();        // seals all warps' reads before overwrite
    }

    // Epilogue: normalize, write single fp16 to ga_h
    float inv0 = 1.f / l0, inv1 = 1.f / l1;
    int t0r = i0 + wm * 16 + (lane >> 2);
#pragma unroll
    for (int nt = 0; nt < 8; nt++) {
        int col = h * 64 + nt * 8 + jcol;
#pragma unroll
        for (int half = 0; half < 2; half++) {
            int t = t0r + half * 8;
            float inv = half ? inv1 : inv0;
            float v0 = oacc[nt][half * 2] * inv;
            float v1 = oacc[nt][half * 2 + 1] * inv;
            __half h0 = __float2half_rn(v0), h1 = __float2half_rn(v1);
            size_t idx = ((size_t)b * Tn + t) * Dn + col;
            *(uint32_t*)&ga_h[idx] =
                (uint32_t)reinterpret_cast<unsigned short&>(h0) |
                ((uint32_t)reinterpret_cast<unsigned short&>(h1) << 16);
        }
    }
}

// ---------------------------------------------------------------------------
extern "C" void kernel_launch(void* const* d_in, const int* in_sizes, int n_in,
                              void* d_out, int out_size)
{
    const float* x   = (const float*)d_in[0];
    const int*   pos = (const int*)d_in[1];
    const float* Wq  = (const float*)d_in[2];
    const float* Wo  = (const float*)d_in[3];
    float* out = (float*)d_out;

    unsigned short *p_xh, *p_wq, *p_wo, *p_gah;
    cudaGetSymbolAddress((void**)&p_xh,  xa_h);
    cudaGetSymbolAddress((void**)&p_wq,  wq_h);
    cudaGetSymbolAddress((void**)&p_wo,  wo_h);
    cudaGetSymbolAddress((void**)&p_gah, ga_h);

    const int GEMM_SMEM = STAGES * STG_BYTES;   // 98304

    // 0) fused fp16 conversions (x, Wqkv, Wout in one launch)
    int nbx  = (Bn * Tn * Dn) / 4 / 256;     // 2048 blocks
    int nbwq = (3 * Dn * Dn) / 4 / 256;      // 3072 blocks
    int nbwo = (Dn * Dn) / 4 / 256;          // 1024 blocks
    conv_fused_kernel<<<nbx + nbwq + nbwo, 256>>>(x, p_xh, Wq, p_wq, Wo, p_wo,
                                                  nbx, nbwq, nbwo);

    // 1) QKV projection -> qkvh
    cudaFuncSetAttribute(tc_gemm<0, 3072>,
                         cudaFuncAttributeMaxDynamicSharedMemorySize, GEMM_SMEM);
    tc_gemm<0, 3072><<<dim3(24, 64), 256, GEMM_SMEM>>>(p_xh, p_wq, nullptr);

    // 2) tensor-core flash attention (128 q-rows / block) -> ga_h
    cudaFuncSetAttribute(attn_mma,
                         cudaFuncAttributeMaxDynamicSharedMemorySize, ATTN_SMEM_SZ);
    attn_mma<<<dim3(Tn / 128, Bn * Hn), 256, ATTN_SMEM_SZ>>>(pos);

    // 3) output projection -> d_out
    cudaFuncSetAttribute(tc_gemm<1, 1024>,
                         cudaFuncAttributeMaxDynamicSharedMemorySize, GEMM_SMEM);
    tc_gemm<1, 1024><<<dim3(8, 64), 256, GEMM_SMEM>>>(p_gah, p_wo, out);
}